// round 9
// baseline (speedup 1.0000x reference)
#include <cuda_runtime.h>
#include <cuda_bf16.h>
#include <cstdint>

// Starcoder2 attention layer on GB300 (sm_103):
//   split -> mma.sync bf16x3 QKV GEMM -> prep(RoPE+scale+split Q/K/V) ->
//   flash attention (mma.sync, bf16x3 scores & PV, online softmax) ->
//   mma.sync bf16x3 O GEMM.
// Fixed shape: T=4096 (B=2,S=2048), HIDDEN=3072, H=24, KH=2, D=128, W=1024.

#define H_      24
#define KH_     2
#define D_      128
#define HIDDEN_ 3072
#define QKV_N_  3584
#define T_MAX_  4096
#define GROUPS_ (H_ / KH_)
#define SCALE_  0.08838834764831845f

// ------------------------- scratch (no cudaMalloc) -------------------------
__device__ float g_qkv[(size_t)T_MAX_ * QKV_N_];
__device__ __nv_bfloat16 g_hs_hi [(size_t)T_MAX_ * HIDDEN_];
__device__ __nv_bfloat16 g_hs_lo [(size_t)T_MAX_ * HIDDEN_];
__device__ __nv_bfloat16 g_att_hi[(size_t)T_MAX_ * HIDDEN_];
__device__ __nv_bfloat16 g_att_lo[(size_t)T_MAX_ * HIDDEN_];
__device__ __nv_bfloat16 g_wqkv_hi[(size_t)QKV_N_ * HIDDEN_];
__device__ __nv_bfloat16 g_wqkv_lo[(size_t)QKV_N_ * HIDDEN_];
__device__ __nv_bfloat16 g_wo_hi [(size_t)HIDDEN_ * HIDDEN_];
__device__ __nv_bfloat16 g_wo_lo [(size_t)HIDDEN_ * HIDDEN_];
// attention operand buffers (post-RoPE, bf16 hi/lo)
__device__ __nv_bfloat16 g_qh[(size_t)T_MAX_ * H_ * D_];
__device__ __nv_bfloat16 g_ql[(size_t)T_MAX_ * H_ * D_];
__device__ __nv_bfloat16 g_kh[(size_t)T_MAX_ * KH_ * D_];
__device__ __nv_bfloat16 g_kl[(size_t)T_MAX_ * KH_ * D_];
__device__ __nv_bfloat16 g_vh[(size_t)T_MAX_ * KH_ * D_];
__device__ __nv_bfloat16 g_vl[(size_t)T_MAX_ * KH_ * D_];

// ------------------------------ helpers ------------------------------------
__device__ __forceinline__ void cp16(uint32_t dst, const void* src) {
    asm volatile("cp.async.cg.shared.global [%0], [%1], 16;" :: "r"(dst), "l"(src));
}
__device__ __forceinline__ void cp_commit() {
    asm volatile("cp.async.commit_group;" ::: "memory");
}
template <int N> __device__ __forceinline__ void cp_wait() {
    asm volatile("cp.async.wait_group %0;" :: "n"(N) : "memory");
}
__device__ __forceinline__ void ldsm_x4(uint32_t* d, uint32_t addr) {
    asm volatile("ldmatrix.sync.aligned.m8n8.x4.shared.b16 {%0,%1,%2,%3}, [%4];"
                 : "=r"(d[0]), "=r"(d[1]), "=r"(d[2]), "=r"(d[3]) : "r"(addr));
}
__device__ __forceinline__ void ldsm_x4_t(uint32_t* d, uint32_t addr) {
    asm volatile("ldmatrix.sync.aligned.m8n8.x4.trans.shared.b16 {%0,%1,%2,%3}, [%4];"
                 : "=r"(d[0]), "=r"(d[1]), "=r"(d[2]), "=r"(d[3]) : "r"(addr));
}
__device__ __forceinline__ void mma_bf16(float* c, const uint32_t* a,
                                         const uint32_t* b) {
    asm volatile(
        "mma.sync.aligned.m16n8k16.row.col.f32.bf16.bf16.f32 "
        "{%0,%1,%2,%3},{%4,%5,%6,%7},{%8,%9},{%0,%1,%2,%3};"
        : "+f"(c[0]), "+f"(c[1]), "+f"(c[2]), "+f"(c[3])
        : "r"(a[0]), "r"(a[1]), "r"(a[2]), "r"(a[3]), "r"(b[0]), "r"(b[1]));
}
__device__ __forceinline__ void split2(float a, float b, uint32_t& hi, uint32_t& lo) {
    __nv_bfloat16 ha = __float2bfloat16(a), hb = __float2bfloat16(b);
    __nv_bfloat16 la = __float2bfloat16(a - __bfloat162float(ha));
    __nv_bfloat16 lb = __float2bfloat16(b - __bfloat162float(hb));
    __nv_bfloat162 Hv(ha, hb), Lv(la, lb);
    hi = *(uint32_t*)&Hv; lo = *(uint32_t*)&Lv;
}
__device__ __forceinline__ void wr_split(__nv_bfloat16* hi, __nv_bfloat16* lo,
                                         size_t idx, float x) {
    __nv_bfloat16 h = __float2bfloat16(x);
    hi[idx] = h;
    lo[idx] = __float2bfloat16(x - __bfloat162float(h));
}
// swizzle for 256B rows, 16B slots
__device__ __forceinline__ uint32_t swz(int row, int slot) {
    return (uint32_t)(row * 256 + ((slot ^ ((row & 7) << 1)) << 4));
}

// --------------------------- split fp32 -> hi/lo ---------------------------
__global__ void split_bf16(const float* __restrict__ src,
                           __nv_bfloat16* __restrict__ hi,
                           __nv_bfloat16* __restrict__ lo, int n4) {
    int i = blockIdx.x * blockDim.x + threadIdx.x;
    if (i >= n4) return;
    float4 v = ((const float4*)src)[i];
    __nv_bfloat16 h0 = __float2bfloat16(v.x);
    __nv_bfloat16 h1 = __float2bfloat16(v.y);
    __nv_bfloat16 h2 = __float2bfloat16(v.z);
    __nv_bfloat16 h3 = __float2bfloat16(v.w);
    __nv_bfloat16 l0 = __float2bfloat16(v.x - __bfloat162float(h0));
    __nv_bfloat16 l1 = __float2bfloat16(v.y - __bfloat162float(h1));
    __nv_bfloat16 l2 = __float2bfloat16(v.z - __bfloat162float(h2));
    __nv_bfloat16 l3 = __float2bfloat16(v.w - __bfloat162float(h3));
    __nv_bfloat162* hp = (__nv_bfloat162*)hi;
    __nv_bfloat162* lp = (__nv_bfloat162*)lo;
    hp[2 * i]     = __nv_bfloat162(h0, h1);
    hp[2 * i + 1] = __nv_bfloat162(h2, h3);
    lp[2 * i]     = __nv_bfloat162(l0, l1);
    lp[2 * i + 1] = __nv_bfloat162(l2, l3);
}

// -------------------- mma.sync bf16x3 GEMM: C = A*B^T + bias ---------------
// 128x128 tile/CTA, 256 threads, 2(M)x4(N) warp grid, BK=32.
// 3-stage cp.async ring, ONE barrier per iteration (loads issued post-barrier).
#define BKE   32
#define TILEB 8192
#define NSTG  3

__global__ __launch_bounds__(256, 2) void gemm_mma(
    const __nv_bfloat16* __restrict__ Ahi, const __nv_bfloat16* __restrict__ Alo,
    const __nv_bfloat16* __restrict__ Bhi, const __nv_bfloat16* __restrict__ Blo,
    const float* __restrict__ bias, float* __restrict__ C,
    int M, int N, int Kd)
{
    __shared__ __align__(128) char sm[NSTG * 2 * TILEB];   // 48KB
    const uint32_t sbase = (uint32_t)__cvta_generic_to_shared(sm);

    const int tid  = threadIdx.x;
    const int lane = tid & 31;
    const int wid  = tid >> 5;
    const int wm   = (wid & 1) * 64;
    const int wn   = (wid >> 1) * 32;
    const int bm   = blockIdx.y * 128;
    const int bn   = blockIdx.x * 128;

    const int nk  = Kd / BKE;
    const int NCH = 3 * nk;

    const __nv_bfloat16* Aps[3] = {Ahi, Ahi, Alo};
    const __nv_bfloat16* Bps[3] = {Bhi, Blo, Bhi};

    const int r0 = (tid) >> 2,        s0 = tid & 3;
    const int r1 = (tid + 256) >> 2,  s1 = tid & 3;
    const uint32_t so0 = (uint32_t)(r0 * 64 + ((s0 ^ ((r0 >> 1) & 3)) << 4));
    const uint32_t so1 = (uint32_t)(r1 * 64 + ((s1 ^ ((r1 >> 1) & 3)) << 4));

    auto load_chunk = [&](int c) {
        const int pass = c / nk;
        const int kk   = (c - pass * nk) * BKE;
        const int st   = c % NSTG;
        const __nv_bfloat16* ga = Aps[pass] + (size_t)bm * Kd + kk;
        const __nv_bfloat16* gb = Bps[pass] + (size_t)bn * Kd + kk;
        const uint32_t sa = sbase + st * (2 * TILEB);
        const uint32_t sb = sa + TILEB;
        cp16(sa + so0, ga + (size_t)r0 * Kd + s0 * 8);
        cp16(sa + so1, ga + (size_t)r1 * Kd + s1 * 8);
        cp16(sb + so0, gb + (size_t)r0 * Kd + s0 * 8);
        cp16(sb + so1, gb + (size_t)r1 * Kd + s1 * 8);
        cp_commit();
    };

    float acc[4][4][4];
#pragma unroll
    for (int i = 0; i < 4; i++)
#pragma unroll
        for (int j = 0; j < 4; j++)
#pragma unroll
            for (int q = 0; q < 4; q++) acc[i][j][q] = 0.0f;

    const int a_row  = wm + ((lane >> 3) & 1) * 8 + (lane & 7);
    const int a_sadd = lane >> 4;
    const int b_rowp = wn + (lane >> 4) * 8 + (lane & 7);
    const int b_sadd = (lane >> 3) & 1;

    load_chunk(0);
    load_chunk(1);

    for (int c = 0; c < NCH; c++) {
        if (c + 1 < NCH) cp_wait<1>(); else cp_wait<0>();
        __syncthreads();
        // Safe post-barrier: stage (c+2)%3's last readers (iter c-1) are all
        // pre-barrier; a fast warp's load(c+3) is fenced by iter c+1's barrier.
        if (c + 2 < NCH) load_chunk(c + 2);

        const int st = c % NSTG;
        const uint32_t sa = sbase + st * (2 * TILEB);
        const uint32_t sb = sa + TILEB;

#pragma unroll
        for (int ks = 0; ks < 2; ks++) {
            uint32_t af[4][4];
#pragma unroll
            for (int mt = 0; mt < 4; mt++) {
                const int r    = a_row + mt * 16;
                const int slot = ks * 2 + a_sadd;
                ldsm_x4(af[mt], sa + r * 64 + (((slot ^ ((r >> 1) & 3))) << 4));
            }
            uint32_t bf[4][2];
#pragma unroll
            for (int p = 0; p < 2; p++) {
                const int r    = b_rowp + p * 16;
                const int slot = ks * 2 + b_sadd;
                uint32_t t4[4];
                ldsm_x4(t4, sb + r * 64 + (((slot ^ ((r >> 1) & 3))) << 4));
                bf[p * 2][0]     = t4[0]; bf[p * 2][1]     = t4[1];
                bf[p * 2 + 1][0] = t4[2]; bf[p * 2 + 1][1] = t4[3];
            }
#pragma unroll
            for (int mt = 0; mt < 4; mt++)
#pragma unroll
                for (int nt = 0; nt < 4; nt++)
                    mma_bf16(acc[mt][nt], af[mt], bf[nt]);
        }
    }

    const int quad = lane >> 2;
    const int tq   = lane & 3;
#pragma unroll
    for (int mt = 0; mt < 4; mt++) {
        const int row = bm + wm + mt * 16 + quad;
#pragma unroll
        for (int nt = 0; nt < 4; nt++) {
            const int col = bn + wn + nt * 8 + tq * 2;
            const float b0 = bias[col], b1 = bias[col + 1];
            float2 v0 = make_float2(acc[mt][nt][0] + b0, acc[mt][nt][1] + b1);
            float2 v1 = make_float2(acc[mt][nt][2] + b0, acc[mt][nt][3] + b1);
            *(float2*)(C + (size_t)row * N + col)       = v0;
            *(float2*)(C + (size_t)(row + 8) * N + col) = v1;
        }
    }
}

// ---------------- prep: RoPE + scale + split into attention layout ---------
__global__ __launch_bounds__(256) void prep_attn(
    const float* __restrict__ cosp, const float* __restrict__ sinp,
    const int* __restrict__ seqp)
{
    const int t = blockIdx.x;
    const int S = seqp[0];
    const int b = t / S, qi = t - b * S;

    for (int task = threadIdx.x; task < 28 * 64; task += blockDim.x) {
        const int hh = task >> 6, d = task & 63;
        const float c = cosp[(size_t)t * 64 + d];
        const float s = sinp[(size_t)t * 64 + d];
        if (hh < H_) {
            const float* src = g_qkv + (size_t)t * QKV_N_ + hh * D_;
            float x1 = src[d], x2 = src[d + 64];
            float y1 = (x1 * c - x2 * s) * SCALE_;
            float y2 = (x2 * c + x1 * s) * SCALE_;
            size_t dst = ((size_t)(b * H_ + hh) * S + qi) * D_;
            wr_split(g_qh, g_ql, dst + d, y1);
            wr_split(g_qh, g_ql, dst + d + 64, y2);
        } else if (hh < H_ + KH_) {
            const int k = hh - H_;
            const float* src = g_qkv + (size_t)t * QKV_N_ + (H_ + k) * D_;
            float x1 = src[d], x2 = src[d + 64];
            float y1 = x1 * c - x2 * s;
            float y2 = x2 * c + x1 * s;
            size_t dst = ((size_t)(b * KH_ + k) * S + qi) * D_;
            wr_split(g_kh, g_kl, dst + d, y1);
            wr_split(g_kh, g_kl, dst + d + 64, y2);
        } else {
            const int v = hh - H_ - KH_;
            const float* src = g_qkv + (size_t)t * QKV_N_ + (H_ + KH_ + v) * D_;
            size_t dst = ((size_t)(b * KH_ + v) * S + qi) * D_;
            wr_split(g_vh, g_vl, dst + d, src[d]);
            wr_split(g_vh, g_vl, dst + d + 64, src[d + 64]);
        }
    }
}

// ------------------------ flash attention (mma.sync) -----------------------
// CTA: 256 queries x 1 head, 512 threads (16 warps x 16 rows), shared KV ring.
// Key blocks of 32, 2-stage cp.async; per-warp block-range skip.
// Scores = Qh*Kh + Qh*Kl + Ql*Kh;  PV = Ph*Vh + Ph*Vl + Pl*Vh.
#define SQH_  0
#define SQL_  65536
#define SSTG_ 131072
#define STGB_ 32768
#define FLASH_SMEM (SSTG_ + 2 * STGB_)   // 196608

__global__ __launch_bounds__(512, 1) void flash_attn(const int* __restrict__ seqp,
                                                     const int* __restrict__ winp)
{
    extern __shared__ __align__(1024) char smf[];
    const uint32_t sb = (uint32_t)__cvta_generic_to_shared(smf);

    const int tid = threadIdx.x, lane = tid & 31, w = tid >> 5;   // w: 0..15
    const int S = seqp[0], W = winp[0];
    const int tau = blockIdx.x * 256;
    const int h   = blockIdx.y;
    const int b   = tau / S, q0 = tau - b * S;
    const int kvh = h / GROUPS_;

    const __nv_bfloat16* qhg = g_qh + ((size_t)(b * H_ + h) * S + q0) * D_;
    const __nv_bfloat16* qlg = g_ql + ((size_t)(b * H_ + h) * S + q0) * D_;
    const size_t kvb = (size_t)(b * KH_ + kvh) * S * D_;

    // Q (hi+lo) -> smem: 256 rows x 256B each buffer, 8 chunks/thread/buffer
#pragma unroll
    for (int i = 0; i < 8; i++) {
        int c = tid + i * 512; int r = c >> 4, sl = c & 15;
        cp16(sb + SQH_ + swz(r, sl), qhg + (size_t)r * D_ + sl * 8);
        cp16(sb + SQL_ + swz(r, sl), qlg + (size_t)r * D_ + sl * 8);
    }
    cp_commit();

    int fk = q0 - W + 1; if (fk < 0) fk = 0;
    const int jb_lo = fk >> 5;
    const int jb_hi = (q0 + 255) >> 5;
    const int nb    = jb_hi - jb_lo + 1;

    // per-warp valid block range (relative to jb_lo); barriers stay global
    const int rw0 = q0 + w * 16;
    int wk0 = rw0 - W + 1; if (wk0 < 0) wk0 = 0;
    const int jwlo = (wk0 >> 5) - jb_lo;
    const int jwhi = ((rw0 + 15) >> 5) - jb_lo;

    // stage load: one 32-key block (Khi/Klo/Vhi/Vlo, 8KB each); 4 cp16/thread
    const int  str = tid >> 4, stl = tid & 15;
    const uint32_t sto = swz(str, stl);
    auto load_stage = [&](int idx) {
        const uint32_t sg = sb + SSTG_ + (idx & 1) * STGB_;
        const size_t go = kvb + (size_t)(jb_lo + idx) * 32 * D_ +
                          (size_t)str * D_ + stl * 8;
        cp16(sg + sto,         g_kh + go);
        cp16(sg + 8192 + sto,  g_kl + go);
        cp16(sg + 16384 + sto, g_vh + go);
        cp16(sg + 24576 + sto, g_vl + go);
        cp_commit();
    };

    load_stage(0);
    if (nb > 1) load_stage(1);

    float o[16][4];
#pragma unroll
    for (int i = 0; i < 16; i++)
#pragma unroll
        for (int e = 0; e < 4; e++) o[i][e] = 0.0f;
    float m[2] = {-1e8f, -1e8f}, l[2] = {0.0f, 0.0f};
    const int qrow = q0 + w * 16 + (lane >> 2);
    const int qr   = w * 16 + (lane & 15);

    for (int i = 0; i < nb; i++) {
        if (i + 1 < nb) cp_wait<1>(); else cp_wait<0>();
        __syncthreads();

        if (i >= jwlo && i <= jwhi) {
            const int jb = jb_lo + i;
            const int j0 = jb * 32;
            const uint32_t stg = sb + SSTG_ + (i & 1) * STGB_;

            // ---- scores (32 keys -> sc[4][4]) ----
            float sc[4][4];
#pragma unroll
            for (int nt = 0; nt < 4; nt++)
#pragma unroll
                for (int e = 0; e < 4; e++) sc[nt][e] = 0.0f;

#pragma unroll
            for (int kc = 0; kc < 8; kc++) {
                uint32_t qh4[4], ql4[4];
                const uint32_t qso = swz(qr, kc * 2 + (lane >> 4));
                ldsm_x4(qh4, sb + SQH_ + qso);
                ldsm_x4(ql4, sb + SQL_ + qso);
#pragma unroll
                for (int ntp = 0; ntp < 2; ntp++) {
                    const int r  = ntp * 16 + ((lane >> 4) << 3) + (lane & 7);
                    const int sl = kc * 2 + ((lane >> 3) & 1);
                    uint32_t t4[4];
                    ldsm_x4(t4, stg + swz(r, sl));                     // Khi
                    uint32_t f0[2] = {t4[0], t4[1]}, f1[2] = {t4[2], t4[3]};
                    mma_bf16(sc[2 * ntp],     qh4, f0);
                    mma_bf16(sc[2 * ntp + 1], qh4, f1);
                    mma_bf16(sc[2 * ntp],     ql4, f0);
                    mma_bf16(sc[2 * ntp + 1], ql4, f1);
                    ldsm_x4(t4, stg + 8192 + swz(r, sl));              // Klo
                    uint32_t g0[2] = {t4[0], t4[1]}, g1[2] = {t4[2], t4[3]};
                    mma_bf16(sc[2 * ntp],     qh4, g0);
                    mma_bf16(sc[2 * ntp + 1], qh4, g1);
                }
            }

            // ---- mask (edge blocks only) ----
            if (j0 < q0 + 256 - W || j0 + 31 > q0) {
#pragma unroll
                for (int nt = 0; nt < 4; nt++)
#pragma unroll
                    for (int e = 0; e < 4; e++) {
                        const int jg = j0 + nt * 8 + ((lane & 3) << 1) + (e & 1);
                        const int qg = qrow + ((e >> 1) << 3);
                        const int dd = qg - jg;
                        if (dd < 0 || dd >= W) sc[nt][e] = -1e9f;
                    }
            }

            // ---- online softmax ----
            float corr[2];
#pragma unroll
            for (int h2 = 0; h2 < 2; h2++) {
                float bm = -1e30f;
#pragma unroll
                for (int nt = 0; nt < 4; nt++)
                    bm = fmaxf(bm, fmaxf(sc[nt][2 * h2], sc[nt][2 * h2 + 1]));
                bm = fmaxf(bm, __shfl_xor_sync(0xffffffffu, bm, 1));
                bm = fmaxf(bm, __shfl_xor_sync(0xffffffffu, bm, 2));
                const float mn = fmaxf(m[h2], bm);
                corr[h2] = __expf(m[h2] - mn);
                m[h2] = mn;
                l[h2] *= corr[h2];
            }
#pragma unroll
            for (int nt = 0; nt < 4; nt++)
#pragma unroll
                for (int e = 0; e < 4; e++) {
                    const float p = __expf(sc[nt][e] - m[e >> 1]);
                    sc[nt][e] = p;
                    l[e >> 1] += p;
                }
#pragma unroll
            for (int nv = 0; nv < 16; nv++) {
                o[nv][0] *= corr[0]; o[nv][1] *= corr[0];
                o[nv][2] *= corr[1]; o[nv][3] *= corr[1];
            }

            // ---- PV (P split hi/lo per 16-key k-tile) ----
#pragma unroll
            for (int t = 0; t < 2; t++) {
                uint32_t ph[4], pl[4];
                split2(sc[2 * t][0],     sc[2 * t][1],     ph[0], pl[0]);
                split2(sc[2 * t][2],     sc[2 * t][3],     ph[1], pl[1]);
                split2(sc[2 * t + 1][0], sc[2 * t + 1][1], ph[2], pl[2]);
                split2(sc[2 * t + 1][2], sc[2 * t + 1][3], ph[3], pl[3]);
                const int r = t * 16 + (lane & 15);
#pragma unroll
                for (int np = 0; np < 8; np++) {
                    const int sl = np * 2 + (lane >> 4);
                    uint32_t t4[4];
                    ldsm_x4_t(t4, stg + 16384 + swz(r, sl));           // Vhi
                    uint32_t f0[2] = {t4[0], t4[1]}, f1[2] = {t4[2], t4[3]};
                    mma_bf16(o[2 * np],     ph, f0);
                    mma_bf16(o[2 * np + 1], ph, f1);
                    mma_bf16(o[2 * np],     pl, f0);
                    mma_bf16(o[2 * np + 1], pl, f1);
                    ldsm_x4_t(t4, stg + 24576 + swz(r, sl));           // Vlo
                    uint32_t g0[2] = {t4[0], t4[1]}, g1[2] = {t4[2], t4[3]};
                    mma_bf16(o[2 * np],     ph, g0);
                    mma_bf16(o[2 * np + 1], ph, g1);
                }
            }
        }

        __syncthreads();
        if (i + 2 < nb) load_stage(i + 2);
    }

    // quad-reduce row sums (lanes sharing a row own disjoint column partials)
#pragma unroll
    for (int h2 = 0; h2 < 2; h2++) {
        l[h2] += __shfl_xor_sync(0xffffffffu, l[h2], 1);
        l[h2] += __shfl_xor_sync(0xffffffffu, l[h2], 2);
    }

    // ---- epilogue: write hi/lo bf16 directly for the O GEMM ----
    const float inv0 = 1.0f / l[0], inv1 = 1.0f / l[1];
    const size_t t0 = (size_t)b * S + qrow;
    const size_t t1 = t0 + 8;
#pragma unroll
    for (int nv = 0; nv < 16; nv++) {
        const int col = h * D_ + nv * 8 + ((lane & 3) << 1);
        uint32_t hi0, lo0, hi1, lo1;
        split2(o[nv][0] * inv0, o[nv][1] * inv0, hi0, lo0);
        split2(o[nv][2] * inv1, o[nv][3] * inv1, hi1, lo1);
        *(uint32_t*)(g_att_hi + t0 * HIDDEN_ + col) = hi0;
        *(uint32_t*)(g_att_lo + t0 * HIDDEN_ + col) = lo0;
        *(uint32_t*)(g_att_hi + t1 * HIDDEN_ + col) = hi1;
        *(uint32_t*)(g_att_lo + t1 * HIDDEN_ + col) = lo1;
    }
}

// --------------------------------- launch ----------------------------------
extern "C" void kernel_launch(void* const* d_in, const int* in_sizes, int n_in,
                              void* d_out, int out_size)
{
    const float* hs   = (const float*)d_in[0];
    const float* wqkv = (const float*)d_in[1];
    const float* bqkv = (const float*)d_in[2];
    const float* wo   = (const float*)d_in[3];
    const float* bo   = (const float*)d_in[4];
    const float* cosp = (const float*)d_in[5];
    const float* sinp = (const float*)d_in[6];
    const int*   seqp = (const int*)d_in[7];
    const int*   winp = (const int*)d_in[8];
    float*       out  = (float*)d_out;

    const int T = in_sizes[0] / HIDDEN_;

    float* qkvbuf;
    __nv_bfloat16 *hs_hi, *hs_lo, *at_hi, *at_lo, *wq_hi, *wq_lo, *wo_hi, *wo_lo;
    cudaGetSymbolAddress((void**)&qkvbuf, g_qkv);
    cudaGetSymbolAddress((void**)&hs_hi, g_hs_hi);
    cudaGetSymbolAddress((void**)&hs_lo, g_hs_lo);
    cudaGetSymbolAddress((void**)&at_hi, g_att_hi);
    cudaGetSymbolAddress((void**)&at_lo, g_att_lo);
    cudaGetSymbolAddress((void**)&wq_hi, g_wqkv_hi);
    cudaGetSymbolAddress((void**)&wq_lo, g_wqkv_lo);
    cudaGetSymbolAddress((void**)&wo_hi, g_wo_hi);
    cudaGetSymbolAddress((void**)&wo_lo, g_wo_lo);

    cudaFuncSetAttribute(flash_attn, cudaFuncAttributeMaxDynamicSharedMemorySize,
                         FLASH_SMEM);

    // splits
    {
        int n4 = T * HIDDEN_ / 4;
        split_bf16<<<(n4 + 255) / 256, 256>>>(hs, hs_hi, hs_lo, n4);
        n4 = QKV_N_ * HIDDEN_ / 4;
        split_bf16<<<(n4 + 255) / 256, 256>>>(wqkv, wq_hi, wq_lo, n4);
        n4 = HIDDEN_ * HIDDEN_ / 4;
        split_bf16<<<(n4 + 255) / 256, 256>>>(wo, wo_hi, wo_lo, n4);
    }
    // QKV GEMM
    {
        dim3 grid(QKV_N_ / 128, T / 128);
        gemm_mma<<<grid, 256>>>(hs_hi, hs_lo, wq_hi, wq_lo, bqkv,
                                qkvbuf, T, QKV_N_, HIDDEN_);
    }
    // RoPE + scale + split into attention operands
    prep_attn<<<T, 256>>>(cosp, sinp, seqp);
    // flash attention: 256 queries per CTA
    {
        dim3 grid(T / 256, H_);
        flash_attn<<<grid, 512, FLASH_SMEM>>>(seqp, winp);
    }
    // O GEMM
    {
        dim3 grid(HIDDEN_ / 128, T / 128);
        gemm_mma<<<grid, 256>>>(at_hi, at_lo, wo_hi, wo_lo, bo,
                                out, T, HIDDEN_, HIDDEN_);
    }
}

// round 13
// speedup vs baseline: 1.1226x; 1.1226x over previous
#include <cuda_runtime.h>
#include <cuda_bf16.h>
#include <cstdint>

// Starcoder2 attention layer on GB300 (sm_103):
//   split -> mma.sync bf16x3 QKV GEMM -> prep(RoPE+scale+split Q/K/V) ->
//   flash attention (mma.sync, bf16x3 scores & PV, online softmax) ->
//   mma.sync bf16x3 O GEMM.
// Fixed shape: T=4096 (B=2,S=2048), HIDDEN=3072, H=24, KH=2, D=128, W=1024.

#define H_      24
#define KH_     2
#define D_      128
#define HIDDEN_ 3072
#define QKV_N_  3584
#define T_MAX_  4096
#define GROUPS_ (H_ / KH_)
#define SCALE_  0.08838834764831845f

// ------------------------- scratch (no cudaMalloc) -------------------------
__device__ float g_qkv[(size_t)T_MAX_ * QKV_N_];
__device__ __nv_bfloat16 g_hs_hi [(size_t)T_MAX_ * HIDDEN_];
__device__ __nv_bfloat16 g_hs_lo [(size_t)T_MAX_ * HIDDEN_];
__device__ __nv_bfloat16 g_att_hi[(size_t)T_MAX_ * HIDDEN_];
__device__ __nv_bfloat16 g_att_lo[(size_t)T_MAX_ * HIDDEN_];
__device__ __nv_bfloat16 g_wqkv_hi[(size_t)QKV_N_ * HIDDEN_];
__device__ __nv_bfloat16 g_wqkv_lo[(size_t)QKV_N_ * HIDDEN_];
__device__ __nv_bfloat16 g_wo_hi [(size_t)HIDDEN_ * HIDDEN_];
__device__ __nv_bfloat16 g_wo_lo [(size_t)HIDDEN_ * HIDDEN_];
// attention operand buffers (post-RoPE, bf16 hi/lo)
__device__ __nv_bfloat16 g_qh[(size_t)T_MAX_ * H_ * D_];
__device__ __nv_bfloat16 g_ql[(size_t)T_MAX_ * H_ * D_];
__device__ __nv_bfloat16 g_kh[(size_t)T_MAX_ * KH_ * D_];
__device__ __nv_bfloat16 g_kl[(size_t)T_MAX_ * KH_ * D_];
__device__ __nv_bfloat16 g_vh[(size_t)T_MAX_ * KH_ * D_];
__device__ __nv_bfloat16 g_vl[(size_t)T_MAX_ * KH_ * D_];

// ------------------------------ helpers ------------------------------------
__device__ __forceinline__ void cp16(uint32_t dst, const void* src) {
    asm volatile("cp.async.cg.shared.global [%0], [%1], 16;" :: "r"(dst), "l"(src));
}
__device__ __forceinline__ void cp_commit() {
    asm volatile("cp.async.commit_group;" ::: "memory");
}
template <int N> __device__ __forceinline__ void cp_wait() {
    asm volatile("cp.async.wait_group %0;" :: "n"(N) : "memory");
}
__device__ __forceinline__ void ldsm_x4(uint32_t* d, uint32_t addr) {
    asm volatile("ldmatrix.sync.aligned.m8n8.x4.shared.b16 {%0,%1,%2,%3}, [%4];"
                 : "=r"(d[0]), "=r"(d[1]), "=r"(d[2]), "=r"(d[3]) : "r"(addr));
}
__device__ __forceinline__ void ldsm_x4_t(uint32_t* d, uint32_t addr) {
    asm volatile("ldmatrix.sync.aligned.m8n8.x4.trans.shared.b16 {%0,%1,%2,%3}, [%4];"
                 : "=r"(d[0]), "=r"(d[1]), "=r"(d[2]), "=r"(d[3]) : "r"(addr));
}
__device__ __forceinline__ void mma_bf16(float* c, const uint32_t* a,
                                         const uint32_t* b) {
    asm volatile(
        "mma.sync.aligned.m16n8k16.row.col.f32.bf16.bf16.f32 "
        "{%0,%1,%2,%3},{%4,%5,%6,%7},{%8,%9},{%0,%1,%2,%3};"
        : "+f"(c[0]), "+f"(c[1]), "+f"(c[2]), "+f"(c[3])
        : "r"(a[0]), "r"(a[1]), "r"(a[2]), "r"(a[3]), "r"(b[0]), "r"(b[1]));
}
__device__ __forceinline__ void split2(float a, float b, uint32_t& hi, uint32_t& lo) {
    __nv_bfloat16 ha = __float2bfloat16(a), hb = __float2bfloat16(b);
    __nv_bfloat16 la = __float2bfloat16(a - __bfloat162float(ha));
    __nv_bfloat16 lb = __float2bfloat16(b - __bfloat162float(hb));
    __nv_bfloat162 Hv(ha, hb), Lv(la, lb);
    hi = *(uint32_t*)&Hv; lo = *(uint32_t*)&Lv;
}
__device__ __forceinline__ void wr_split(__nv_bfloat16* hi, __nv_bfloat16* lo,
                                         size_t idx, float x) {
    __nv_bfloat16 h = __float2bfloat16(x);
    hi[idx] = h;
    lo[idx] = __float2bfloat16(x - __bfloat162float(h));
}
// swizzle for 256B rows, 16B slots (flash kernel)
__device__ __forceinline__ uint32_t swz(int row, int slot) {
    return (uint32_t)(row * 256 + ((slot ^ ((row & 7) << 1)) << 4));
}

// --------------------------- split fp32 -> hi/lo ---------------------------
__global__ void split_bf16(const float* __restrict__ src,
                           __nv_bfloat16* __restrict__ hi,
                           __nv_bfloat16* __restrict__ lo, int n4) {
    int i = blockIdx.x * blockDim.x + threadIdx.x;
    if (i >= n4) return;
    float4 v = ((const float4*)src)[i];
    __nv_bfloat16 h0 = __float2bfloat16(v.x);
    __nv_bfloat16 h1 = __float2bfloat16(v.y);
    __nv_bfloat16 h2 = __float2bfloat16(v.z);
    __nv_bfloat16 h3 = __float2bfloat16(v.w);
    __nv_bfloat16 l0 = __float2bfloat16(v.x - __bfloat162float(h0));
    __nv_bfloat16 l1 = __float2bfloat16(v.y - __bfloat162float(h1));
    __nv_bfloat16 l2 = __float2bfloat16(v.z - __bfloat162float(h2));
    __nv_bfloat16 l3 = __float2bfloat16(v.w - __bfloat162float(h3));
    __nv_bfloat162* hp = (__nv_bfloat162*)hi;
    __nv_bfloat162* lp = (__nv_bfloat162*)lo;
    hp[2 * i]     = __nv_bfloat162(h0, h1);
    hp[2 * i + 1] = __nv_bfloat162(h2, h3);
    lp[2 * i]     = __nv_bfloat162(l0, l1);
    lp[2 * i + 1] = __nv_bfloat162(l2, l3);
}

// -------------------- mma.sync bf16x3 GEMM: C = A*B^T + bias ---------------
// 128x128 tile/CTA, 256 threads, 2(M)x4(N) warp grid.  BK=64 (R10 change):
// 2-stage cp.async double buffer, R8 barrier rhythm, half the iterations.
// Smem tile rows are 128B / 8 slots of 16B; slot s at row r -> s ^ (r & 7).
#define BKE   64
#define TILEB 16384               // 128 rows * 128B
#define NSTG  2

__global__ __launch_bounds__(256, 2) void gemm_mma(
    const __nv_bfloat16* __restrict__ Ahi, const __nv_bfloat16* __restrict__ Alo,
    const __nv_bfloat16* __restrict__ Bhi, const __nv_bfloat16* __restrict__ Blo,
    const float* __restrict__ bias, float* __restrict__ C,
    int M, int N, int Kd)
{
    __shared__ __align__(128) char sm[NSTG * 2 * TILEB];   // 64KB
    const uint32_t sbase = (uint32_t)__cvta_generic_to_shared(sm);

    const int tid  = threadIdx.x;
    const int lane = tid & 31;
    const int wid  = tid >> 5;
    const int wm   = (wid & 1) * 64;
    const int wn   = (wid >> 1) * 32;
    const int bm   = blockIdx.y * 128;
    const int bn   = blockIdx.x * 128;

    const int nk  = Kd / BKE;     // 48
    const int NCH = 3 * nk;       // 144

    const __nv_bfloat16* Aps[3] = {Ahi, Ahi, Alo};
    const __nv_bfloat16* Bps[3] = {Bhi, Blo, Bhi};

    // gmem->smem: 4 x 16B chunks of A and of B per thread (1024 chunks/tile)
    int rr[4], sl[4];
    uint32_t so[4];
#pragma unroll
    for (int i = 0; i < 4; i++) {
        const int lin = tid + i * 256;
        rr[i] = lin >> 3;
        sl[i] = lin & 7;
        so[i] = (uint32_t)(rr[i] * 128 + ((sl[i] ^ (rr[i] & 7)) << 4));
    }

    auto load_chunk = [&](int c) {
        const int pass = c / nk;
        const int kk   = (c - pass * nk) * BKE;
        const int st   = c & (NSTG - 1);
        const __nv_bfloat16* ga = Aps[pass] + (size_t)bm * Kd + kk;
        const __nv_bfloat16* gb = Bps[pass] + (size_t)bn * Kd + kk;
        const uint32_t sa = sbase + st * (2 * TILEB);
        const uint32_t sb = sa + TILEB;
#pragma unroll
        for (int i = 0; i < 4; i++) {
            cp16(sa + so[i], ga + (size_t)rr[i] * Kd + sl[i] * 8);
            cp16(sb + so[i], gb + (size_t)rr[i] * Kd + sl[i] * 8);
        }
        cp_commit();
    };

    float acc[4][4][4];
#pragma unroll
    for (int i = 0; i < 4; i++)
#pragma unroll
        for (int j = 0; j < 4; j++)
#pragma unroll
            for (int q = 0; q < 4; q++) acc[i][j][q] = 0.0f;

    const int a_row  = wm + ((lane >> 3) & 1) * 8 + (lane & 7);
    const int a_sadd = lane >> 4;
    const int b_rowp = wn + (lane >> 4) * 8 + (lane & 7);
    const int b_sadd = (lane >> 3) & 1;

    load_chunk(0);

    for (int c = 0; c < NCH; c++) {
        if (c + 1 < NCH) { load_chunk(c + 1); cp_wait<1>(); }
        else             { cp_wait<0>(); }
        __syncthreads();

        const uint32_t sa = sbase + (c & (NSTG - 1)) * (2 * TILEB);
        const uint32_t sb = sa + TILEB;

#pragma unroll
        for (int ks = 0; ks < 4; ks++) {
            uint32_t af[4][4];
#pragma unroll
            for (int mt = 0; mt < 4; mt++) {
                const int r    = a_row + mt * 16;
                const int slot = ks * 2 + a_sadd;
                ldsm_x4(af[mt], sa + r * 128 + (((slot ^ (r & 7))) << 4));
            }
            uint32_t bf[4][2];
#pragma unroll
            for (int p = 0; p < 2; p++) {
                const int r    = b_rowp + p * 16;
                const int slot = ks * 2 + b_sadd;
                uint32_t t4[4];
                ldsm_x4(t4, sb + r * 128 + (((slot ^ (r & 7))) << 4));
                bf[p * 2][0]     = t4[0]; bf[p * 2][1]     = t4[1];
                bf[p * 2 + 1][0] = t4[2]; bf[p * 2 + 1][1] = t4[3];
            }
#pragma unroll
            for (int mt = 0; mt < 4; mt++)
#pragma unroll
                for (int nt = 0; nt < 4; nt++)
                    mma_bf16(acc[mt][nt], af[mt], bf[nt]);
        }
        __syncthreads();
    }

    const int quad = lane >> 2;
    const int tq   = lane & 3;
#pragma unroll
    for (int mt = 0; mt < 4; mt++) {
        const int row = bm + wm + mt * 16 + quad;
#pragma unroll
        for (int nt = 0; nt < 4; nt++) {
            const int col = bn + wn + nt * 8 + tq * 2;
            const float b0 = bias[col], b1 = bias[col + 1];
            float2 v0 = make_float2(acc[mt][nt][0] + b0, acc[mt][nt][1] + b1);
            float2 v1 = make_float2(acc[mt][nt][2] + b0, acc[mt][nt][3] + b1);
            *(float2*)(C + (size_t)row * N + col)       = v0;
            *(float2*)(C + (size_t)(row + 8) * N + col) = v1;
        }
    }
}

// ---------------- prep: RoPE + scale + split into attention layout ---------
__global__ __launch_bounds__(256) void prep_attn(
    const float* __restrict__ cosp, const float* __restrict__ sinp,
    const int* __restrict__ seqp)
{
    const int t = blockIdx.x;
    const int S = seqp[0];
    const int b = t / S, qi = t - b * S;

    for (int task = threadIdx.x; task < 28 * 64; task += blockDim.x) {
        const int hh = task >> 6, d = task & 63;
        const float c = cosp[(size_t)t * 64 + d];
        const float s = sinp[(size_t)t * 64 + d];
        if (hh < H_) {
            const float* src = g_qkv + (size_t)t * QKV_N_ + hh * D_;
            float x1 = src[d], x2 = src[d + 64];
            float y1 = (x1 * c - x2 * s) * SCALE_;
            float y2 = (x2 * c + x1 * s) * SCALE_;
            size_t dst = ((size_t)(b * H_ + hh) * S + qi) * D_;
            wr_split(g_qh, g_ql, dst + d, y1);
            wr_split(g_qh, g_ql, dst + d + 64, y2);
        } else if (hh < H_ + KH_) {
            const int k = hh - H_;
            const float* src = g_qkv + (size_t)t * QKV_N_ + (H_ + k) * D_;
            float x1 = src[d], x2 = src[d + 64];
            float y1 = x1 * c - x2 * s;
            float y2 = x2 * c + x1 * s;
            size_t dst = ((size_t)(b * KH_ + k) * S + qi) * D_;
            wr_split(g_kh, g_kl, dst + d, y1);
            wr_split(g_kh, g_kl, dst + d + 64, y2);
        } else {
            const int v = hh - H_ - KH_;
            const float* src = g_qkv + (size_t)t * QKV_N_ + (H_ + KH_ + v) * D_;
            size_t dst = ((size_t)(b * KH_ + v) * S + qi) * D_;
            wr_split(g_vh, g_vl, dst + d, src[d]);
            wr_split(g_vh, g_vl, dst + d + 64, src[d + 64]);
        }
    }
}

// ------------------------ flash attention (mma.sync) -----------------------
// R8-winning version, unchanged: CTA = 128 queries x 1 head; 8 warps x 16
// rows; key blocks of 64; 2-stage cp.async.
// Scores = Qh*Kh + Qh*Kl + Ql*Kh;  PV = Ph*Vh + Ph*Vl + Pl*Vh.
#define SQH_  0
#define SQL_  32768
#define SSTG_ 65536
#define STGB_ 65536
#define FLASH_SMEM (SSTG_ + 2 * STGB_)   // 196608

__global__ __launch_bounds__(256, 1) void flash_attn(const int* __restrict__ seqp,
                                                     const int* __restrict__ winp)
{
    extern __shared__ __align__(1024) char smf[];
    const uint32_t sb = (uint32_t)__cvta_generic_to_shared(smf);

    const int tid = threadIdx.x, lane = tid & 31, w = tid >> 5;
    const int S = seqp[0], W = winp[0];
    const int tau = blockIdx.x * 128;
    const int h   = blockIdx.y;
    const int b   = tau / S, q0 = tau - b * S;
    const int kvh = h / GROUPS_;

    const __nv_bfloat16* qhg = g_qh + ((size_t)(b * H_ + h) * S + q0) * D_;
    const __nv_bfloat16* qlg = g_ql + ((size_t)(b * H_ + h) * S + q0) * D_;
    const size_t kvb = (size_t)(b * KH_ + kvh) * S * D_;

    // Q (hi+lo) -> smem
#pragma unroll
    for (int i = 0; i < 8; i++) {
        int c = tid + i * 256; int r = c >> 4, sl = c & 15;
        cp16(sb + SQH_ + swz(r, sl), qhg + (size_t)r * D_ + sl * 8);
        cp16(sb + SQL_ + swz(r, sl), qlg + (size_t)r * D_ + sl * 8);
    }
    cp_commit();

    int fk = q0 - W + 1; if (fk < 0) fk = 0;
    const int jb_lo = fk >> 6;
    const int jb_hi = (q0 + 127) >> 6;
    const int nb    = jb_hi - jb_lo + 1;

    auto load_stage = [&](int idx) {
        const int jb = jb_lo + idx;
        const uint32_t sg = sb + SSTG_ + (idx & 1) * STGB_;
        const size_t gofs = kvb + (size_t)jb * 64 * D_;
#pragma unroll
        for (int i = 0; i < 4; i++) {
            int c = tid + i * 256; int r = c >> 4, sl = c & 15;
            const uint32_t so = swz(r, sl);
            const size_t go = gofs + (size_t)r * D_ + sl * 8;
            cp16(sg + so,         g_kh + go);
            cp16(sg + 16384 + so, g_kl + go);
            cp16(sg + 32768 + so, g_vh + go);
            cp16(sg + 49152 + so, g_vl + go);
        }
        cp_commit();
    };

    load_stage(0);
    load_stage(1);

    // Q fragments (hi resident; lo re-read per block)
    cp_wait<2>();
    __syncthreads();
    uint32_t qhf[8][4];
    {
        const int r = w * 16 + (lane & 15);
#pragma unroll
        for (int kc = 0; kc < 8; kc++)
            ldsm_x4(qhf[kc], sb + SQH_ + swz(r, kc * 2 + (lane >> 4)));
    }

    float o[16][4];
#pragma unroll
    for (int i = 0; i < 16; i++)
#pragma unroll
        for (int e = 0; e < 4; e++) o[i][e] = 0.0f;
    float m[2] = {-1e8f, -1e8f}, l[2] = {0.0f, 0.0f};
    const int qrow = q0 + w * 16 + (lane >> 2);

    for (int i = 0; i < nb; i++) {
        if (i + 1 < nb) cp_wait<1>(); else cp_wait<0>();
        __syncthreads();
        const int jb = jb_lo + i;
        const uint32_t stg = sb + SSTG_ + (i & 1) * STGB_;

        // ---- scores ----
        float sc[8][4];
#pragma unroll
        for (int nt = 0; nt < 8; nt++)
#pragma unroll
            for (int e = 0; e < 4; e++) sc[nt][e] = 0.0f;

#pragma unroll
        for (int kc = 0; kc < 8; kc++) {
            uint32_t qlf[4];
            {
                const int r = w * 16 + (lane & 15);
                ldsm_x4(qlf, sb + SQL_ + swz(r, kc * 2 + (lane >> 4)));
            }
#pragma unroll
            for (int ntp = 0; ntp < 4; ntp++) {
                const int r  = ntp * 16 + ((lane >> 4) << 3) + (lane & 7);
                const int sl = kc * 2 + ((lane >> 3) & 1);
                uint32_t t4[4];
                ldsm_x4(t4, stg + swz(r, sl));                       // Khi
                uint32_t f0[2] = {t4[0], t4[1]}, f1[2] = {t4[2], t4[3]};
                mma_bf16(sc[2 * ntp],     qhf[kc], f0);
                mma_bf16(sc[2 * ntp + 1], qhf[kc], f1);
                mma_bf16(sc[2 * ntp],     qlf,     f0);
                mma_bf16(sc[2 * ntp + 1], qlf,     f1);
                ldsm_x4(t4, stg + 16384 + swz(r, sl));               // Klo
                uint32_t g0[2] = {t4[0], t4[1]}, g1[2] = {t4[2], t4[3]};
                mma_bf16(sc[2 * ntp],     qhf[kc], g0);
                mma_bf16(sc[2 * ntp + 1], qhf[kc], g1);
            }
        }

        // ---- mask (edge blocks only) ----
        const int j0 = jb * 64;
        if (j0 < q0 + 128 - W || j0 + 63 > q0) {
#pragma unroll
            for (int nt = 0; nt < 8; nt++)
#pragma unroll
                for (int e = 0; e < 4; e++) {
                    const int jg = j0 + nt * 8 + ((lane & 3) << 1) + (e & 1);
                    const int qg = qrow + ((e >> 1) << 3);
                    const int dd = qg - jg;
                    if (dd < 0 || dd >= W) sc[nt][e] = -1e9f;
                }
        }

        // ---- online softmax ----
        float corr[2];
#pragma unroll
        for (int h2 = 0; h2 < 2; h2++) {
            float bm = -1e30f;
#pragma unroll
            for (int nt = 0; nt < 8; nt++)
                bm = fmaxf(bm, fmaxf(sc[nt][2 * h2], sc[nt][2 * h2 + 1]));
            bm = fmaxf(bm, __shfl_xor_sync(0xffffffffu, bm, 1));
            bm = fmaxf(bm, __shfl_xor_sync(0xffffffffu, bm, 2));
            const float mn = fmaxf(m[h2], bm);
            corr[h2] = __expf(m[h2] - mn);
            m[h2] = mn;
            l[h2] *= corr[h2];
        }
#pragma unroll
        for (int nt = 0; nt < 8; nt++)
#pragma unroll
            for (int e = 0; e < 4; e++) {
                const float p = __expf(sc[nt][e] - m[e >> 1]);
                sc[nt][e] = p;
                l[e >> 1] += p;
            }
#pragma unroll
        for (int nv = 0; nv < 16; nv++) {
            o[nv][0] *= corr[0]; o[nv][1] *= corr[0];
            o[nv][2] *= corr[1]; o[nv][3] *= corr[1];
        }

        // ---- P fragments (hi/lo) ----
        uint32_t ph[4][4], pl[4][4];
#pragma unroll
        for (int t = 0; t < 4; t++) {
            split2(sc[2 * t][0],     sc[2 * t][1],     ph[t][0], pl[t][0]);
            split2(sc[2 * t][2],     sc[2 * t][3],     ph[t][1], pl[t][1]);
            split2(sc[2 * t + 1][0], sc[2 * t + 1][1], ph[t][2], pl[t][2]);
            split2(sc[2 * t + 1][2], sc[2 * t + 1][3], ph[t][3], pl[t][3]);
        }

        // ---- PV ----
#pragma unroll
        for (int t = 0; t < 4; t++) {
            const int r = t * 16 + (lane & 15);
#pragma unroll
            for (int np = 0; np < 8; np++) {
                const int sl = np * 2 + (lane >> 4);
                uint32_t t4[4];
                ldsm_x4_t(t4, stg + 32768 + swz(r, sl));             // Vhi
                uint32_t f0[2] = {t4[0], t4[1]}, f1[2] = {t4[2], t4[3]};
                mma_bf16(o[2 * np],     ph[t], f0);
                mma_bf16(o[2 * np + 1], ph[t], f1);
                mma_bf16(o[2 * np],     pl[t], f0);
                mma_bf16(o[2 * np + 1], pl[t], f1);
                ldsm_x4_t(t4, stg + 49152 + swz(r, sl));             // Vlo
                uint32_t g0[2] = {t4[0], t4[1]}, g1[2] = {t4[2], t4[3]};
                mma_bf16(o[2 * np],     ph[t], g0);
                mma_bf16(o[2 * np + 1], ph[t], g1);
            }
        }

        __syncthreads();
        if (i + 2 < nb) load_stage(i + 2);
    }

    // quad-reduce row sums (lanes sharing a row own disjoint column partials)
#pragma unroll
    for (int h2 = 0; h2 < 2; h2++) {
        l[h2] += __shfl_xor_sync(0xffffffffu, l[h2], 1);
        l[h2] += __shfl_xor_sync(0xffffffffu, l[h2], 2);
    }

    // ---- epilogue: write hi/lo bf16 directly for the O GEMM ----
    const float inv0 = 1.0f / l[0], inv1 = 1.0f / l[1];
    const size_t t0 = (size_t)b * S + qrow;
    const size_t t1 = t0 + 8;
#pragma unroll
    for (int nv = 0; nv < 16; nv++) {
        const int col = h * D_ + nv * 8 + ((lane & 3) << 1);
        uint32_t hi0, lo0, hi1, lo1;
        split2(o[nv][0] * inv0, o[nv][1] * inv0, hi0, lo0);
        split2(o[nv][2] * inv1, o[nv][3] * inv1, hi1, lo1);
        *(uint32_t*)(g_att_hi + t0 * HIDDEN_ + col) = hi0;
        *(uint32_t*)(g_att_lo + t0 * HIDDEN_ + col) = lo0;
        *(uint32_t*)(g_att_hi + t1 * HIDDEN_ + col) = hi1;
        *(uint32_t*)(g_att_lo + t1 * HIDDEN_ + col) = lo1;
    }
}

// --------------------------------- launch ----------------------------------
extern "C" void kernel_launch(void* const* d_in, const int* in_sizes, int n_in,
                              void* d_out, int out_size)
{
    const float* hs   = (const float*)d_in[0];
    const float* wqkv = (const float*)d_in[1];
    const float* bqkv = (const float*)d_in[2];
    const float* wo   = (const float*)d_in[3];
    const float* bo   = (const float*)d_in[4];
    const float* cosp = (const float*)d_in[5];
    const float* sinp = (const float*)d_in[6];
    const int*   seqp = (const int*)d_in[7];
    const int*   winp = (const int*)d_in[8];
    float*       out  = (float*)d_out;

    const int T = in_sizes[0] / HIDDEN_;

    float* qkvbuf;
    __nv_bfloat16 *hs_hi, *hs_lo, *at_hi, *at_lo, *wq_hi, *wq_lo, *wo_hi, *wo_lo;
    cudaGetSymbolAddress((void**)&qkvbuf, g_qkv);
    cudaGetSymbolAddress((void**)&hs_hi, g_hs_hi);
    cudaGetSymbolAddress((void**)&hs_lo, g_hs_lo);
    cudaGetSymbolAddress((void**)&at_hi, g_att_hi);
    cudaGetSymbolAddress((void**)&at_lo, g_att_lo);
    cudaGetSymbolAddress((void**)&wq_hi, g_wqkv_hi);
    cudaGetSymbolAddress((void**)&wq_lo, g_wqkv_lo);
    cudaGetSymbolAddress((void**)&wo_hi, g_wo_hi);
    cudaGetSymbolAddress((void**)&wo_lo, g_wo_lo);

    cudaFuncSetAttribute(flash_attn, cudaFuncAttributeMaxDynamicSharedMemorySize,
                         FLASH_SMEM);

    // splits
    {
        int n4 = T * HIDDEN_ / 4;
        split_bf16<<<(n4 + 255) / 256, 256>>>(hs, hs_hi, hs_lo, n4);
        n4 = QKV_N_ * HIDDEN_ / 4;
        split_bf16<<<(n4 + 255) / 256, 256>>>(wqkv, wq_hi, wq_lo, n4);
        n4 = HIDDEN_ * HIDDEN_ / 4;
        split_bf16<<<(n4 + 255) / 256, 256>>>(wo, wo_hi, wo_lo, n4);
    }
    // QKV GEMM
    {
        dim3 grid(QKV_N_ / 128, T / 128);
        gemm_mma<<<grid, 256>>>(hs_hi, hs_lo, wq_hi, wq_lo, bqkv,
                                qkvbuf, T, QKV_N_, HIDDEN_);
    }
    // RoPE + scale + split into attention operands
    prep_attn<<<T, 256>>>(cosp, sinp, seqp);
    // flash attention
    {
        dim3 grid(T / 128, H_);
        flash_attn<<<grid, 256, FLASH_SMEM>>>(seqp, winp);
    }
    // O GEMM
    {
        dim3 grid(HIDDEN_ / 128, T / 128);
        gemm_mma<<<grid, 256>>>(at_hi, at_lo, wo_hi, wo_lo, bo,
                                out, T, HIDDEN_, HIDDEN_);
    }
}

// round 15
// speedup vs baseline: 1.1742x; 1.0460x over previous
#include <cuda_runtime.h>
#include <cuda_bf16.h>
#include <cstdint>

// Starcoder2 attention layer on GB300 (sm_103):
//   split -> mma.sync bf16x3 QKV GEMM -> prep(RoPE+scale+split Q/K/V) ->
//   flash attention (mma.sync, bf16x3 scores & PV, online softmax, exp2) ->
//   mma.sync bf16x3 O GEMM.
// Fixed shape: T=4096 (B=2,S=2048), HIDDEN=3072, H=24, KH=2, D=128, W=1024.

#define H_      24
#define KH_     2
#define D_      128
#define HIDDEN_ 3072
#define QKV_N_  3584
#define T_MAX_  4096
#define GROUPS_ (H_ / KH_)
// Q pre-scale: 1/sqrt(D) * log2(e)  (flash softmax works in exp2 domain)
#define QSCALE_ 0.12753057419890419f

// ------------------------- scratch (no cudaMalloc) -------------------------
__device__ float g_qkv[(size_t)T_MAX_ * QKV_N_];
__device__ __nv_bfloat16 g_hs_hi [(size_t)T_MAX_ * HIDDEN_];
__device__ __nv_bfloat16 g_hs_lo [(size_t)T_MAX_ * HIDDEN_];
__device__ __nv_bfloat16 g_att_hi[(size_t)T_MAX_ * HIDDEN_];
__device__ __nv_bfloat16 g_att_lo[(size_t)T_MAX_ * HIDDEN_];
__device__ __nv_bfloat16 g_wqkv_hi[(size_t)QKV_N_ * HIDDEN_];
__device__ __nv_bfloat16 g_wqkv_lo[(size_t)QKV_N_ * HIDDEN_];
__device__ __nv_bfloat16 g_wo_hi [(size_t)HIDDEN_ * HIDDEN_];
__device__ __nv_bfloat16 g_wo_lo [(size_t)HIDDEN_ * HIDDEN_];
// attention operand buffers (post-RoPE, bf16 hi/lo)
__device__ __nv_bfloat16 g_qh[(size_t)T_MAX_ * H_ * D_];
__device__ __nv_bfloat16 g_ql[(size_t)T_MAX_ * H_ * D_];
__device__ __nv_bfloat16 g_kh[(size_t)T_MAX_ * KH_ * D_];
__device__ __nv_bfloat16 g_kl[(size_t)T_MAX_ * KH_ * D_];
__device__ __nv_bfloat16 g_vh[(size_t)T_MAX_ * KH_ * D_];
__device__ __nv_bfloat16 g_vl[(size_t)T_MAX_ * KH_ * D_];

// ------------------------------ helpers ------------------------------------
__device__ __forceinline__ void cp16(uint32_t dst, const void* src) {
    asm volatile("cp.async.cg.shared.global [%0], [%1], 16;" :: "r"(dst), "l"(src));
}
__device__ __forceinline__ void cp_commit() {
    asm volatile("cp.async.commit_group;" ::: "memory");
}
template <int N> __device__ __forceinline__ void cp_wait() {
    asm volatile("cp.async.wait_group %0;" :: "n"(N) : "memory");
}
__device__ __forceinline__ void ldsm_x4(uint32_t* d, uint32_t addr) {
    asm volatile("ldmatrix.sync.aligned.m8n8.x4.shared.b16 {%0,%1,%2,%3}, [%4];"
                 : "=r"(d[0]), "=r"(d[1]), "=r"(d[2]), "=r"(d[3]) : "r"(addr));
}
__device__ __forceinline__ void ldsm_x4_t(uint32_t* d, uint32_t addr) {
    asm volatile("ldmatrix.sync.aligned.m8n8.x4.trans.shared.b16 {%0,%1,%2,%3}, [%4];"
                 : "=r"(d[0]), "=r"(d[1]), "=r"(d[2]), "=r"(d[3]) : "r"(addr));
}
__device__ __forceinline__ void mma_bf16(float* c, const uint32_t* a,
                                         const uint32_t* b) {
    asm volatile(
        "mma.sync.aligned.m16n8k16.row.col.f32.bf16.bf16.f32 "
        "{%0,%1,%2,%3},{%4,%5,%6,%7},{%8,%9},{%0,%1,%2,%3};"
        : "+f"(c[0]), "+f"(c[1]), "+f"(c[2]), "+f"(c[3])
        : "r"(a[0]), "r"(a[1]), "r"(a[2]), "r"(a[3]), "r"(b[0]), "r"(b[1]));
}
__device__ __forceinline__ float ex2(float x) {
    float r;
    asm("ex2.approx.ftz.f32 %0, %1;" : "=f"(r) : "f"(x));
    return r;
}
__device__ __forceinline__ void split2(float a, float b, uint32_t& hi, uint32_t& lo) {
    __nv_bfloat16 ha = __float2bfloat16(a), hb = __float2bfloat16(b);
    __nv_bfloat16 la = __float2bfloat16(a - __bfloat162float(ha));
    __nv_bfloat16 lb = __float2bfloat16(b - __bfloat162float(hb));
    __nv_bfloat162 Hv(ha, hb), Lv(la, lb);
    hi = *(uint32_t*)&Hv; lo = *(uint32_t*)&Lv;
}
__device__ __forceinline__ void wr_split(__nv_bfloat16* hi, __nv_bfloat16* lo,
                                         size_t idx, float x) {
    __nv_bfloat16 h = __float2bfloat16(x);
    hi[idx] = h;
    lo[idx] = __float2bfloat16(x - __bfloat162float(h));
}
// swizzle for 256B rows, 16B slots (flash kernel)
__device__ __forceinline__ uint32_t swz(int row, int slot) {
    return (uint32_t)(row * 256 + ((slot ^ ((row & 7) << 1)) << 4));
}

// --------------------------- split fp32 -> hi/lo ---------------------------
__global__ void split_bf16(const float* __restrict__ src,
                           __nv_bfloat16* __restrict__ hi,
                           __nv_bfloat16* __restrict__ lo, int n4) {
    int i = blockIdx.x * blockDim.x + threadIdx.x;
    if (i >= n4) return;
    float4 v = ((const float4*)src)[i];
    __nv_bfloat16 h0 = __float2bfloat16(v.x);
    __nv_bfloat16 h1 = __float2bfloat16(v.y);
    __nv_bfloat16 h2 = __float2bfloat16(v.z);
    __nv_bfloat16 h3 = __float2bfloat16(v.w);
    __nv_bfloat16 l0 = __float2bfloat16(v.x - __bfloat162float(h0));
    __nv_bfloat16 l1 = __float2bfloat16(v.y - __bfloat162float(h1));
    __nv_bfloat16 l2 = __float2bfloat16(v.z - __bfloat162float(h2));
    __nv_bfloat16 l3 = __float2bfloat16(v.w - __bfloat162float(h3));
    __nv_bfloat162* hp = (__nv_bfloat162*)hi;
    __nv_bfloat162* lp = (__nv_bfloat162*)lo;
    hp[2 * i]     = __nv_bfloat162(h0, h1);
    hp[2 * i + 1] = __nv_bfloat162(h2, h3);
    lp[2 * i]     = __nv_bfloat162(l0, l1);
    lp[2 * i + 1] = __nv_bfloat162(l2, l3);
}

// -------------------- mma.sync bf16x3 GEMM (R8-winning config) -------------
// 128x128 tile/CTA, 256 threads, 2(M)x4(N) warp grid, BK=32, 2-stage.
#define BKE   32
#define TILEB 8192
#define NSTG  2

__global__ __launch_bounds__(256, 2) void gemm_mma(
    const __nv_bfloat16* __restrict__ Ahi, const __nv_bfloat16* __restrict__ Alo,
    const __nv_bfloat16* __restrict__ Bhi, const __nv_bfloat16* __restrict__ Blo,
    const float* __restrict__ bias, float* __restrict__ C,
    int M, int N, int Kd)
{
    __shared__ __align__(128) char sm[NSTG * 2 * TILEB];
    const uint32_t sbase = (uint32_t)__cvta_generic_to_shared(sm);

    const int tid  = threadIdx.x;
    const int lane = tid & 31;
    const int wid  = tid >> 5;
    const int wm   = (wid & 1) * 64;
    const int wn   = (wid >> 1) * 32;
    const int bm   = blockIdx.y * 128;
    const int bn   = blockIdx.x * 128;

    const int nk  = Kd / BKE;
    const int NCH = 3 * nk;

    const __nv_bfloat16* Aps[3] = {Ahi, Ahi, Alo};
    const __nv_bfloat16* Bps[3] = {Bhi, Blo, Bhi};

    const int r0 = (tid) >> 2,        s0 = tid & 3;
    const int r1 = (tid + 256) >> 2,  s1 = tid & 3;
    const uint32_t so0 = (uint32_t)(r0 * 64 + ((s0 ^ ((r0 >> 1) & 3)) << 4));
    const uint32_t so1 = (uint32_t)(r1 * 64 + ((s1 ^ ((r1 >> 1) & 3)) << 4));

    auto load_chunk = [&](int c) {
        const int pass = c / nk;
        const int kk   = (c - pass * nk) * BKE;
        const int st   = c & (NSTG - 1);
        const __nv_bfloat16* ga = Aps[pass] + (size_t)bm * Kd + kk;
        const __nv_bfloat16* gb = Bps[pass] + (size_t)bn * Kd + kk;
        const uint32_t sa = sbase + st * (2 * TILEB);
        const uint32_t sb = sa + TILEB;
        cp16(sa + so0, ga + (size_t)r0 * Kd + s0 * 8);
        cp16(sa + so1, ga + (size_t)r1 * Kd + s1 * 8);
        cp16(sb + so0, gb + (size_t)r0 * Kd + s0 * 8);
        cp16(sb + so1, gb + (size_t)r1 * Kd + s1 * 8);
        cp_commit();
    };

    float acc[4][4][4];
#pragma unroll
    for (int i = 0; i < 4; i++)
#pragma unroll
        for (int j = 0; j < 4; j++)
#pragma unroll
            for (int q = 0; q < 4; q++) acc[i][j][q] = 0.0f;

    const int a_row  = wm + ((lane >> 3) & 1) * 8 + (lane & 7);
    const int a_sadd = lane >> 4;
    const int b_rowp = wn + (lane >> 4) * 8 + (lane & 7);
    const int b_sadd = (lane >> 3) & 1;

    load_chunk(0);

    for (int c = 0; c < NCH; c++) {
        if (c + 1 < NCH) { load_chunk(c + 1); cp_wait<1>(); }
        else             { cp_wait<0>(); }
        __syncthreads();

        const uint32_t sa = sbase + (c & (NSTG - 1)) * (2 * TILEB);
        const uint32_t sb = sa + TILEB;

#pragma unroll
        for (int ks = 0; ks < 2; ks++) {
            uint32_t af[4][4];
#pragma unroll
            for (int mt = 0; mt < 4; mt++) {
                const int r    = a_row + mt * 16;
                const int slot = ks * 2 + a_sadd;
                ldsm_x4(af[mt], sa + r * 64 + (((slot ^ ((r >> 1) & 3))) << 4));
            }
            uint32_t bf[4][2];
#pragma unroll
            for (int p = 0; p < 2; p++) {
                const int r    = b_rowp + p * 16;
                const int slot = ks * 2 + b_sadd;
                uint32_t t4[4];
                ldsm_x4(t4, sb + r * 64 + (((slot ^ ((r >> 1) & 3))) << 4));
                bf[p * 2][0]     = t4[0]; bf[p * 2][1]     = t4[1];
                bf[p * 2 + 1][0] = t4[2]; bf[p * 2 + 1][1] = t4[3];
            }
#pragma unroll
            for (int mt = 0; mt < 4; mt++)
#pragma unroll
                for (int nt = 0; nt < 4; nt++)
                    mma_bf16(acc[mt][nt], af[mt], bf[nt]);
        }
        __syncthreads();
    }

    const int quad = lane >> 2;
    const int tq   = lane & 3;
#pragma unroll
    for (int mt = 0; mt < 4; mt++) {
        const int row = bm + wm + mt * 16 + quad;
#pragma unroll
        for (int nt = 0; nt < 4; nt++) {
            const int col = bn + wn + nt * 8 + tq * 2;
            const float b0 = bias[col], b1 = bias[col + 1];
            float2 v0 = make_float2(acc[mt][nt][0] + b0, acc[mt][nt][1] + b1);
            float2 v1 = make_float2(acc[mt][nt][2] + b0, acc[mt][nt][3] + b1);
            *(float2*)(C + (size_t)row * N + col)       = v0;
            *(float2*)(C + (size_t)(row + 8) * N + col) = v1;
        }
    }
}

// ---------------- prep: RoPE + scale + split into attention layout ---------
// Q is pre-scaled by 1/sqrt(D) * log2(e): flash softmax runs in exp2 domain.
__global__ __launch_bounds__(256) void prep_attn(
    const float* __restrict__ cosp, const float* __restrict__ sinp,
    const int* __restrict__ seqp)
{
    const int t = blockIdx.x;
    const int S = seqp[0];
    const int b = t / S, qi = t - b * S;

    for (int task = threadIdx.x; task < 28 * 64; task += blockDim.x) {
        const int hh = task >> 6, d = task & 63;
        const float c = cosp[(size_t)t * 64 + d];
        const float s = sinp[(size_t)t * 64 + d];
        if (hh < H_) {
            const float* src = g_qkv + (size_t)t * QKV_N_ + hh * D_;
            float x1 = src[d], x2 = src[d + 64];
            float y1 = (x1 * c - x2 * s) * QSCALE_;
            float y2 = (x2 * c + x1 * s) * QSCALE_;
            size_t dst = ((size_t)(b * H_ + hh) * S + qi) * D_;
            wr_split(g_qh, g_ql, dst + d, y1);
            wr_split(g_qh, g_ql, dst + d + 64, y2);
        } else if (hh < H_ + KH_) {
            const int k = hh - H_;
            const float* src = g_qkv + (size_t)t * QKV_N_ + (H_ + k) * D_;
            float x1 = src[d], x2 = src[d + 64];
            float y1 = x1 * c - x2 * s;
            float y2 = x2 * c + x1 * s;
            size_t dst = ((size_t)(b * KH_ + k) * S + qi) * D_;
            wr_split(g_kh, g_kl, dst + d, y1);
            wr_split(g_kh, g_kl, dst + d + 64, y2);
        } else {
            const int v = hh - H_ - KH_;
            const float* src = g_qkv + (size_t)t * QKV_N_ + (H_ + KH_ + v) * D_;
            size_t dst = ((size_t)(b * KH_ + v) * S + qi) * D_;
            wr_split(g_vh, g_vl, dst + d, src[d]);
            wr_split(g_vh, g_vl, dst + d + 64, src[d + 64]);
        }
    }
}

// ------------------------ flash attention (mma.sync) -----------------------
// R8 structure: CTA = 128 queries x 1 head; 8 warps x 16 rows; 64-key blocks;
// 2-stage cp.async.  R14 additions: per-warp block-range skip, exp2-domain
// softmax, per-warp mask tightening, Q-lo fragments register-resident.
// Scores = Qh*Kh + Qh*Kl + Ql*Kh;  PV = Ph*Vh + Ph*Vl + Pl*Vh.
#define SQH_  0
#define SQL_  32768
#define SSTG_ 65536
#define STGB_ 65536
#define FLASH_SMEM (SSTG_ + 2 * STGB_)   // 196608

__global__ __launch_bounds__(256, 1) void flash_attn(const int* __restrict__ seqp,
                                                     const int* __restrict__ winp)
{
    extern __shared__ __align__(1024) char smf[];
    const uint32_t sb = (uint32_t)__cvta_generic_to_shared(smf);

    const int tid = threadIdx.x, lane = tid & 31, w = tid >> 5;
    const int S = seqp[0], W = winp[0];
    const int tau = blockIdx.x * 128;
    const int h   = blockIdx.y;
    const int b   = tau / S, q0 = tau - b * S;
    const int kvh = h / GROUPS_;

    const __nv_bfloat16* qhg = g_qh + ((size_t)(b * H_ + h) * S + q0) * D_;
    const __nv_bfloat16* qlg = g_ql + ((size_t)(b * H_ + h) * S + q0) * D_;
    const size_t kvb = (size_t)(b * KH_ + kvh) * S * D_;

    // Q (hi+lo) -> smem
#pragma unroll
    for (int i = 0; i < 8; i++) {
        int c = tid + i * 256; int r = c >> 4, sl = c & 15;
        cp16(sb + SQH_ + swz(r, sl), qhg + (size_t)r * D_ + sl * 8);
        cp16(sb + SQL_ + swz(r, sl), qlg + (size_t)r * D_ + sl * 8);
    }
    cp_commit();

    int fk = q0 - W + 1; if (fk < 0) fk = 0;
    const int jb_lo = fk >> 6;
    const int jb_hi = (q0 + 127) >> 6;
    const int nb    = jb_hi - jb_lo + 1;

    // per-warp valid block range (relative indices); barriers stay global
    const int rw0 = q0 + w * 16;
    int wk0 = rw0 - W + 1; if (wk0 < 0) wk0 = 0;
    const int jwlo = (wk0 >> 6) - jb_lo;
    const int jwhi = ((rw0 + 15) >> 6) - jb_lo;

    auto load_stage = [&](int idx) {
        const int jb = jb_lo + idx;
        const uint32_t sg = sb + SSTG_ + (idx & 1) * STGB_;
        const size_t gofs = kvb + (size_t)jb * 64 * D_;
#pragma unroll
        for (int i = 0; i < 4; i++) {
            int c = tid + i * 256; int r = c >> 4, sl = c & 15;
            const uint32_t so = swz(r, sl);
            const size_t go = gofs + (size_t)r * D_ + sl * 8;
            cp16(sg + so,         g_kh + go);
            cp16(sg + 16384 + so, g_kl + go);
            cp16(sg + 32768 + so, g_vh + go);
            cp16(sg + 49152 + so, g_vl + go);
        }
        cp_commit();
    };

    load_stage(0);
    load_stage(1);

    // Q fragments: hi AND lo register-resident (1 CTA/SM -> 256-reg budget)
    cp_wait<2>();
    __syncthreads();
    uint32_t qhf[8][4], qlf[8][4];
    {
        const int r = w * 16 + (lane & 15);
#pragma unroll
        for (int kc = 0; kc < 8; kc++) {
            const uint32_t qso = swz(r, kc * 2 + (lane >> 4));
            ldsm_x4(qhf[kc], sb + SQH_ + qso);
            ldsm_x4(qlf[kc], sb + SQL_ + qso);
        }
    }

    float o[16][4];
#pragma unroll
    for (int i = 0; i < 16; i++)
#pragma unroll
        for (int e = 0; e < 4; e++) o[i][e] = 0.0f;
    float m[2] = {-1e8f, -1e8f}, l[2] = {0.0f, 0.0f};
    const int qrow = q0 + w * 16 + (lane >> 2);

    for (int i = 0; i < nb; i++) {
        if (i + 1 < nb) cp_wait<1>(); else cp_wait<0>();
        __syncthreads();

        if (i >= jwlo && i <= jwhi) {
            const int jb = jb_lo + i;
            const uint32_t stg = sb + SSTG_ + (i & 1) * STGB_;

            // ---- scores ----
            float sc[8][4];
#pragma unroll
            for (int nt = 0; nt < 8; nt++)
#pragma unroll
                for (int e = 0; e < 4; e++) sc[nt][e] = 0.0f;

#pragma unroll
            for (int kc = 0; kc < 8; kc++) {
#pragma unroll
                for (int ntp = 0; ntp < 4; ntp++) {
                    const int r  = ntp * 16 + ((lane >> 4) << 3) + (lane & 7);
                    const int sl = kc * 2 + ((lane >> 3) & 1);
                    uint32_t t4[4];
                    ldsm_x4(t4, stg + swz(r, sl));                     // Khi
                    uint32_t f0[2] = {t4[0], t4[1]}, f1[2] = {t4[2], t4[3]};
                    mma_bf16(sc[2 * ntp],     qhf[kc], f0);
                    mma_bf16(sc[2 * ntp + 1], qhf[kc], f1);
                    mma_bf16(sc[2 * ntp],     qlf[kc], f0);
                    mma_bf16(sc[2 * ntp + 1], qlf[kc], f1);
                    ldsm_x4(t4, stg + 16384 + swz(r, sl));             // Klo
                    uint32_t g0[2] = {t4[0], t4[1]}, g1[2] = {t4[2], t4[3]};
                    mma_bf16(sc[2 * ntp],     qhf[kc], g0);
                    mma_bf16(sc[2 * ntp + 1], qhf[kc], g1);
                }
            }

            // ---- mask (per-warp edge blocks only) ----
            const int j0 = jb * 64;
            if (j0 < rw0 + 16 - W || j0 + 63 > rw0) {
#pragma unroll
                for (int nt = 0; nt < 8; nt++)
#pragma unroll
                    for (int e = 0; e < 4; e++) {
                        const int jg = j0 + nt * 8 + ((lane & 3) << 1) + (e & 1);
                        const int qg = qrow + ((e >> 1) << 3);
                        const int dd = qg - jg;
                        if (dd < 0 || dd >= W) sc[nt][e] = -1e9f;
                    }
            }

            // ---- online softmax (exp2 domain: Q pre-scaled by log2e) ----
            float corr[2];
#pragma unroll
            for (int h2 = 0; h2 < 2; h2++) {
                float bm = -1e30f;
#pragma unroll
                for (int nt = 0; nt < 8; nt++)
                    bm = fmaxf(bm, fmaxf(sc[nt][2 * h2], sc[nt][2 * h2 + 1]));
                bm = fmaxf(bm, __shfl_xor_sync(0xffffffffu, bm, 1));
                bm = fmaxf(bm, __shfl_xor_sync(0xffffffffu, bm, 2));
                const float mn = fmaxf(m[h2], bm);
                corr[h2] = ex2(m[h2] - mn);
                m[h2] = mn;
                l[h2] *= corr[h2];
            }
#pragma unroll
            for (int nt = 0; nt < 8; nt++)
#pragma unroll
                for (int e = 0; e < 4; e++) {
                    const float p = ex2(sc[nt][e] - m[e >> 1]);
                    sc[nt][e] = p;
                    l[e >> 1] += p;
                }
#pragma unroll
            for (int nv = 0; nv < 16; nv++) {
                o[nv][0] *= corr[0]; o[nv][1] *= corr[0];
                o[nv][2] *= corr[1]; o[nv][3] *= corr[1];
            }

            // ---- P fragments (hi/lo) + PV ----
#pragma unroll
            for (int t = 0; t < 4; t++) {
                uint32_t ph[4], pl[4];
                split2(sc[2 * t][0],     sc[2 * t][1],     ph[0], pl[0]);
                split2(sc[2 * t][2],     sc[2 * t][3],     ph[1], pl[1]);
                split2(sc[2 * t + 1][0], sc[2 * t + 1][1], ph[2], pl[2]);
                split2(sc[2 * t + 1][2], sc[2 * t + 1][3], ph[3], pl[3]);
                const int r = t * 16 + (lane & 15);
#pragma unroll
                for (int np = 0; np < 8; np++) {
                    const int sl = np * 2 + (lane >> 4);
                    uint32_t t4[4];
                    ldsm_x4_t(t4, stg + 32768 + swz(r, sl));           // Vhi
                    uint32_t f0[2] = {t4[0], t4[1]}, f1[2] = {t4[2], t4[3]};
                    mma_bf16(o[2 * np],     ph, f0);
                    mma_bf16(o[2 * np + 1], ph, f1);
                    mma_bf16(o[2 * np],     pl, f0);
                    mma_bf16(o[2 * np + 1], pl, f1);
                    ldsm_x4_t(t4, stg + 49152 + swz(r, sl));           // Vlo
                    uint32_t g0[2] = {t4[0], t4[1]}, g1[2] = {t4[2], t4[3]};
                    mma_bf16(o[2 * np],     ph, g0);
                    mma_bf16(o[2 * np + 1], ph, g1);
                }
            }
        }

        __syncthreads();
        if (i + 2 < nb) load_stage(i + 2);
    }

    // quad-reduce row sums (lanes sharing a row own disjoint column partials)
#pragma unroll
    for (int h2 = 0; h2 < 2; h2++) {
        l[h2] += __shfl_xor_sync(0xffffffffu, l[h2], 1);
        l[h2] += __shfl_xor_sync(0xffffffffu, l[h2], 2);
    }

    // ---- epilogue: write hi/lo bf16 directly for the O GEMM ----
    const float inv0 = 1.0f / l[0], inv1 = 1.0f / l[1];
    const size_t t0 = (size_t)b * S + qrow;
    const size_t t1 = t0 + 8;
#pragma unroll
    for (int nv = 0; nv < 16; nv++) {
        const int col = h * D_ + nv * 8 + ((lane & 3) << 1);
        uint32_t hi0, lo0, hi1, lo1;
        split2(o[nv][0] * inv0, o[nv][1] * inv0, hi0, lo0);
        split2(o[nv][2] * inv1, o[nv][3] * inv1, hi1, lo1);
        *(uint32_t*)(g_att_hi + t0 * HIDDEN_ + col) = hi0;
        *(uint32_t*)(g_att_lo + t0 * HIDDEN_ + col) = lo0;
        *(uint32_t*)(g_att_hi + t1 * HIDDEN_ + col) = hi1;
        *(uint32_t*)(g_att_lo + t1 * HIDDEN_ + col) = lo1;
    }
}

// --------------------------------- launch ----------------------------------
extern "C" void kernel_launch(void* const* d_in, const int* in_sizes, int n_in,
                              void* d_out, int out_size)
{
    const float* hs   = (const float*)d_in[0];
    const float* wqkv = (const float*)d_in[1];
    const float* bqkv = (const float*)d_in[2];
    const float* wo   = (const float*)d_in[3];
    const float* bo   = (const float*)d_in[4];
    const float* cosp = (const float*)d_in[5];
    const float* sinp = (const float*)d_in[6];
    const int*   seqp = (const int*)d_in[7];
    const int*   winp = (const int*)d_in[8];
    float*       out  = (float*)d_out;

    const int T = in_sizes[0] / HIDDEN_;

    float* qkvbuf;
    __nv_bfloat16 *hs_hi, *hs_lo, *at_hi, *at_lo, *wq_hi, *wq_lo, *wo_hi, *wo_lo;
    cudaGetSymbolAddress((void**)&qkvbuf, g_qkv);
    cudaGetSymbolAddress((void**)&hs_hi, g_hs_hi);
    cudaGetSymbolAddress((void**)&hs_lo, g_hs_lo);
    cudaGetSymbolAddress((void**)&at_hi, g_att_hi);
    cudaGetSymbolAddress((void**)&at_lo, g_att_lo);
    cudaGetSymbolAddress((void**)&wq_hi, g_wqkv_hi);
    cudaGetSymbolAddress((void**)&wq_lo, g_wqkv_lo);
    cudaGetSymbolAddress((void**)&wo_hi, g_wo_hi);
    cudaGetSymbolAddress((void**)&wo_lo, g_wo_lo);

    cudaFuncSetAttribute(flash_attn, cudaFuncAttributeMaxDynamicSharedMemorySize,
                         FLASH_SMEM);

    // splits
    {
        int n4 = T * HIDDEN_ / 4;
        split_bf16<<<(n4 + 255) / 256, 256>>>(hs, hs_hi, hs_lo, n4);
        n4 = QKV_N_ * HIDDEN_ / 4;
        split_bf16<<<(n4 + 255) / 256, 256>>>(wqkv, wq_hi, wq_lo, n4);
        n4 = HIDDEN_ * HIDDEN_ / 4;
        split_bf16<<<(n4 + 255) / 256, 256>>>(wo, wo_hi, wo_lo, n4);
    }
    // QKV GEMM
    {
        dim3 grid(QKV_N_ / 128, T / 128);
        gemm_mma<<<grid, 256>>>(hs_hi, hs_lo, wq_hi, wq_lo, bqkv,
                                qkvbuf, T, QKV_N_, HIDDEN_);
    }
    // RoPE + scale + split into attention operands
    prep_attn<<<T, 256>>>(cosp, sinp, seqp);
    // flash attention
    {
        dim3 grid(T / 128, H_);
        flash_attn<<<grid, 256, FLASH_SMEM>>>(seqp, winp);
    }
    // O GEMM
    {
        dim3 grid(HIDDEN_ / 128, T / 128);
        gemm_mma<<<grid, 256>>>(at_hi, at_lo, wo_hi, wo_lo, bo,
                                out, T, HIDDEN_, HIDDEN_);
    }
}

// round 16
// speedup vs baseline: 1.2074x; 1.0283x over previous
#include <cuda_runtime.h>
#include <cuda_bf16.h>
#include <cstdint>

// Starcoder2 attention layer on GB300 (sm_103):
//   split -> mma.sync bf16x3 QKV GEMM (fused 3-combo chunks) ->
//   prep(RoPE+scale+split) -> flash attention (mma.sync, bf16x3, exp2) ->
//   mma.sync bf16x3 O GEMM.
// Fixed shape: T=4096 (B=2,S=2048), HIDDEN=3072, H=24, KH=2, D=128, W=1024.

#define H_      24
#define KH_     2
#define D_      128
#define HIDDEN_ 3072
#define QKV_N_  3584
#define T_MAX_  4096
#define GROUPS_ (H_ / KH_)
// Q pre-scale: 1/sqrt(D) * log2(e)  (flash softmax works in exp2 domain)
#define QSCALE_ 0.12753057419890419f

// ------------------------- scratch (no cudaMalloc) -------------------------
__device__ float g_qkv[(size_t)T_MAX_ * QKV_N_];
__device__ __nv_bfloat16 g_hs_hi [(size_t)T_MAX_ * HIDDEN_];
__device__ __nv_bfloat16 g_hs_lo [(size_t)T_MAX_ * HIDDEN_];
__device__ __nv_bfloat16 g_att_hi[(size_t)T_MAX_ * HIDDEN_];
__device__ __nv_bfloat16 g_att_lo[(size_t)T_MAX_ * HIDDEN_];
__device__ __nv_bfloat16 g_wqkv_hi[(size_t)QKV_N_ * HIDDEN_];
__device__ __nv_bfloat16 g_wqkv_lo[(size_t)QKV_N_ * HIDDEN_];
__device__ __nv_bfloat16 g_wo_hi [(size_t)HIDDEN_ * HIDDEN_];
__device__ __nv_bfloat16 g_wo_lo [(size_t)HIDDEN_ * HIDDEN_];
// attention operand buffers (post-RoPE, bf16 hi/lo)
__device__ __nv_bfloat16 g_qh[(size_t)T_MAX_ * H_ * D_];
__device__ __nv_bfloat16 g_ql[(size_t)T_MAX_ * H_ * D_];
__device__ __nv_bfloat16 g_kh[(size_t)T_MAX_ * KH_ * D_];
__device__ __nv_bfloat16 g_kl[(size_t)T_MAX_ * KH_ * D_];
__device__ __nv_bfloat16 g_vh[(size_t)T_MAX_ * KH_ * D_];
__device__ __nv_bfloat16 g_vl[(size_t)T_MAX_ * KH_ * D_];

// ------------------------------ helpers ------------------------------------
__device__ __forceinline__ void cp16(uint32_t dst, const void* src) {
    asm volatile("cp.async.cg.shared.global [%0], [%1], 16;" :: "r"(dst), "l"(src));
}
__device__ __forceinline__ void cp_commit() {
    asm volatile("cp.async.commit_group;" ::: "memory");
}
template <int N> __device__ __forceinline__ void cp_wait() {
    asm volatile("cp.async.wait_group %0;" :: "n"(N) : "memory");
}
__device__ __forceinline__ void ldsm_x4(uint32_t* d, uint32_t addr) {
    asm volatile("ldmatrix.sync.aligned.m8n8.x4.shared.b16 {%0,%1,%2,%3}, [%4];"
                 : "=r"(d[0]), "=r"(d[1]), "=r"(d[2]), "=r"(d[3]) : "r"(addr));
}
__device__ __forceinline__ void ldsm_x4_t(uint32_t* d, uint32_t addr) {
    asm volatile("ldmatrix.sync.aligned.m8n8.x4.trans.shared.b16 {%0,%1,%2,%3}, [%4];"
                 : "=r"(d[0]), "=r"(d[1]), "=r"(d[2]), "=r"(d[3]) : "r"(addr));
}
__device__ __forceinline__ void mma_bf16(float* c, const uint32_t* a,
                                         const uint32_t* b) {
    asm volatile(
        "mma.sync.aligned.m16n8k16.row.col.f32.bf16.bf16.f32 "
        "{%0,%1,%2,%3},{%4,%5,%6,%7},{%8,%9},{%0,%1,%2,%3};"
        : "+f"(c[0]), "+f"(c[1]), "+f"(c[2]), "+f"(c[3])
        : "r"(a[0]), "r"(a[1]), "r"(a[2]), "r"(a[3]), "r"(b[0]), "r"(b[1]));
}
__device__ __forceinline__ float ex2(float x) {
    float r;
    asm("ex2.approx.ftz.f32 %0, %1;" : "=f"(r) : "f"(x));
    return r;
}
__device__ __forceinline__ void split2(float a, float b, uint32_t& hi, uint32_t& lo) {
    __nv_bfloat16 ha = __float2bfloat16(a), hb = __float2bfloat16(b);
    __nv_bfloat16 la = __float2bfloat16(a - __bfloat162float(ha));
    __nv_bfloat16 lb = __float2bfloat16(b - __bfloat162float(hb));
    __nv_bfloat162 Hv(ha, hb), Lv(la, lb);
    hi = *(uint32_t*)&Hv; lo = *(uint32_t*)&Lv;
}
__device__ __forceinline__ void wr_split(__nv_bfloat16* hi, __nv_bfloat16* lo,
                                         size_t idx, float x) {
    __nv_bfloat16 h = __float2bfloat16(x);
    hi[idx] = h;
    lo[idx] = __float2bfloat16(x - __bfloat162float(h));
}
// swizzle for 256B rows, 16B slots (flash kernel)
__device__ __forceinline__ uint32_t swz(int row, int slot) {
    return (uint32_t)(row * 256 + ((slot ^ ((row & 7) << 1)) << 4));
}

// --------------------------- split fp32 -> hi/lo ---------------------------
__global__ void split_bf16(const float* __restrict__ src,
                           __nv_bfloat16* __restrict__ hi,
                           __nv_bfloat16* __restrict__ lo, int n4) {
    int i = blockIdx.x * blockDim.x + threadIdx.x;
    if (i >= n4) return;
    float4 v = ((const float4*)src)[i];
    __nv_bfloat16 h0 = __float2bfloat16(v.x);
    __nv_bfloat16 h1 = __float2bfloat16(v.y);
    __nv_bfloat16 h2 = __float2bfloat16(v.z);
    __nv_bfloat16 h3 = __float2bfloat16(v.w);
    __nv_bfloat16 l0 = __float2bfloat16(v.x - __bfloat162float(h0));
    __nv_bfloat16 l1 = __float2bfloat16(v.y - __bfloat162float(h1));
    __nv_bfloat16 l2 = __float2bfloat16(v.z - __bfloat162float(h2));
    __nv_bfloat16 l3 = __float2bfloat16(v.w - __bfloat162float(h3));
    __nv_bfloat162* hp = (__nv_bfloat162*)hi;
    __nv_bfloat162* lp = (__nv_bfloat162*)lo;
    hp[2 * i]     = __nv_bfloat162(h0, h1);
    hp[2 * i + 1] = __nv_bfloat162(h2, h3);
    lp[2 * i]     = __nv_bfloat162(l0, l1);
    lp[2 * i + 1] = __nv_bfloat162(l2, l3);
}

// -------------------- mma.sync bf16x3 GEMM: C = A*B^T + bias ---------------
// 128x128 tile/CTA, 256 threads, 2(M)x4(N) warp grid, BK=32, 2-stage.
// R16: each chunk loads FOUR tiles (Ahi,Alo,Bhi,Blo) and runs all three
// compensation combos (hh, h*lo, lo*h) against one smem residency:
// 96 iterations instead of 288, 1/3 the barriers, 2/3 the gmem chunks.
#define BKE   32
#define TILEB 8192
#define STGB4 (4 * TILEB)         // 32KB per stage
#define NSTG  2

__global__ __launch_bounds__(256, 2) void gemm_mma(
    const __nv_bfloat16* __restrict__ Ahi, const __nv_bfloat16* __restrict__ Alo,
    const __nv_bfloat16* __restrict__ Bhi, const __nv_bfloat16* __restrict__ Blo,
    const float* __restrict__ bias, float* __restrict__ C,
    int M, int N, int Kd)
{
    __shared__ __align__(128) char sm[NSTG * STGB4];       // 64KB
    const uint32_t sbase = (uint32_t)__cvta_generic_to_shared(sm);

    const int tid  = threadIdx.x;
    const int lane = tid & 31;
    const int wid  = tid >> 5;
    const int wm   = (wid & 1) * 64;
    const int wn   = (wid >> 1) * 32;
    const int bm   = blockIdx.y * 128;
    const int bn   = blockIdx.x * 128;

    const int nk = Kd / BKE;      // 96 chunks

    const int r0 = (tid) >> 2,        s0 = tid & 3;
    const int r1 = (tid + 256) >> 2,  s1 = tid & 3;
    const uint32_t so0 = (uint32_t)(r0 * 64 + ((s0 ^ ((r0 >> 1) & 3)) << 4));
    const uint32_t so1 = (uint32_t)(r1 * 64 + ((s1 ^ ((r1 >> 1) & 3)) << 4));

    auto load_chunk = [&](int c) {
        const int kk = c * BKE;
        const int st = c & (NSTG - 1);
        const uint32_t sg = sbase + st * STGB4;
        const __nv_bfloat16* gah = Ahi + (size_t)bm * Kd + kk;
        const __nv_bfloat16* gal = Alo + (size_t)bm * Kd + kk;
        const __nv_bfloat16* gbh = Bhi + (size_t)bn * Kd + kk;
        const __nv_bfloat16* gbl = Blo + (size_t)bn * Kd + kk;
        cp16(sg + so0,             gah + (size_t)r0 * Kd + s0 * 8);
        cp16(sg + so1,             gah + (size_t)r1 * Kd + s1 * 8);
        cp16(sg + TILEB + so0,     gal + (size_t)r0 * Kd + s0 * 8);
        cp16(sg + TILEB + so1,     gal + (size_t)r1 * Kd + s1 * 8);
        cp16(sg + 2 * TILEB + so0, gbh + (size_t)r0 * Kd + s0 * 8);
        cp16(sg + 2 * TILEB + so1, gbh + (size_t)r1 * Kd + s1 * 8);
        cp16(sg + 3 * TILEB + so0, gbl + (size_t)r0 * Kd + s0 * 8);
        cp16(sg + 3 * TILEB + so1, gbl + (size_t)r1 * Kd + s1 * 8);
        cp_commit();
    };

    float acc[4][4][4];
#pragma unroll
    for (int i = 0; i < 4; i++)
#pragma unroll
        for (int j = 0; j < 4; j++)
#pragma unroll
            for (int q = 0; q < 4; q++) acc[i][j][q] = 0.0f;

    const int a_row  = wm + ((lane >> 3) & 1) * 8 + (lane & 7);
    const int a_sadd = lane >> 4;
    const int b_rowp = wn + (lane >> 4) * 8 + (lane & 7);
    const int b_sadd = (lane >> 3) & 1;

    load_chunk(0);

    for (int c = 0; c < nk; c++) {
        if (c + 1 < nk) { load_chunk(c + 1); cp_wait<1>(); }
        else            { cp_wait<0>(); }
        __syncthreads();

        const uint32_t sg = sbase + (c & (NSTG - 1)) * STGB4;

#pragma unroll
        for (int ks = 0; ks < 2; ks++) {
            // ---- A-hi fragments ----
            uint32_t afh[4][4];
#pragma unroll
            for (int mt = 0; mt < 4; mt++) {
                const int r    = a_row + mt * 16;
                const int slot = ks * 2 + a_sadd;
                ldsm_x4(afh[mt], sg + r * 64 + (((slot ^ ((r >> 1) & 3))) << 4));
            }
            // ---- B-hi fragments + combo hh ----
            uint32_t bfh[4][2];
#pragma unroll
            for (int p = 0; p < 2; p++) {
                const int r    = b_rowp + p * 16;
                const int slot = ks * 2 + b_sadd;
                uint32_t t4[4];
                ldsm_x4(t4, sg + 2 * TILEB + r * 64 +
                              (((slot ^ ((r >> 1) & 3))) << 4));
                bfh[p * 2][0]     = t4[0]; bfh[p * 2][1]     = t4[1];
                bfh[p * 2 + 1][0] = t4[2]; bfh[p * 2 + 1][1] = t4[3];
            }
#pragma unroll
            for (int mt = 0; mt < 4; mt++)
#pragma unroll
                for (int nt = 0; nt < 4; nt++)
                    mma_bf16(acc[mt][nt], afh[mt], bfh[nt]);

            // ---- B-lo fragments + combo Ahi*Blo ----
            {
                uint32_t bfl[4][2];
#pragma unroll
                for (int p = 0; p < 2; p++) {
                    const int r    = b_rowp + p * 16;
                    const int slot = ks * 2 + b_sadd;
                    uint32_t t4[4];
                    ldsm_x4(t4, sg + 3 * TILEB + r * 64 +
                                  (((slot ^ ((r >> 1) & 3))) << 4));
                    bfl[p * 2][0]     = t4[0]; bfl[p * 2][1]     = t4[1];
                    bfl[p * 2 + 1][0] = t4[2]; bfl[p * 2 + 1][1] = t4[3];
                }
#pragma unroll
                for (int mt = 0; mt < 4; mt++)
#pragma unroll
                    for (int nt = 0; nt < 4; nt++)
                        mma_bf16(acc[mt][nt], afh[mt], bfl[nt]);
            }

            // ---- A-lo fragments + combo Alo*Bhi ----
            {
                uint32_t afl[4];
#pragma unroll
                for (int mt = 0; mt < 4; mt++) {
                    const int r    = a_row + mt * 16;
                    const int slot = ks * 2 + a_sadd;
                    ldsm_x4(afl, sg + TILEB + r * 64 +
                                   (((slot ^ ((r >> 1) & 3))) << 4));
#pragma unroll
                    for (int nt = 0; nt < 4; nt++)
                        mma_bf16(acc[mt][nt], afl, bfh[nt]);
                }
            }
        }
        __syncthreads();
    }

    const int quad = lane >> 2;
    const int tq   = lane & 3;
#pragma unroll
    for (int mt = 0; mt < 4; mt++) {
        const int row = bm + wm + mt * 16 + quad;
#pragma unroll
        for (int nt = 0; nt < 4; nt++) {
            const int col = bn + wn + nt * 8 + tq * 2;
            const float b0 = bias[col], b1 = bias[col + 1];
            float2 v0 = make_float2(acc[mt][nt][0] + b0, acc[mt][nt][1] + b1);
            float2 v1 = make_float2(acc[mt][nt][2] + b0, acc[mt][nt][3] + b1);
            *(float2*)(C + (size_t)row * N + col)       = v0;
            *(float2*)(C + (size_t)(row + 8) * N + col) = v1;
        }
    }
}

// ---------------- prep: RoPE + scale + split into attention layout ---------
// Q is pre-scaled by 1/sqrt(D) * log2(e): flash softmax runs in exp2 domain.
__global__ __launch_bounds__(256) void prep_attn(
    const float* __restrict__ cosp, const float* __restrict__ sinp,
    const int* __restrict__ seqp)
{
    const int t = blockIdx.x;
    const int S = seqp[0];
    const int b = t / S, qi = t - b * S;

    for (int task = threadIdx.x; task < 28 * 64; task += blockDim.x) {
        const int hh = task >> 6, d = task & 63;
        const float c = cosp[(size_t)t * 64 + d];
        const float s = sinp[(size_t)t * 64 + d];
        if (hh < H_) {
            const float* src = g_qkv + (size_t)t * QKV_N_ + hh * D_;
            float x1 = src[d], x2 = src[d + 64];
            float y1 = (x1 * c - x2 * s) * QSCALE_;
            float y2 = (x2 * c + x1 * s) * QSCALE_;
            size_t dst = ((size_t)(b * H_ + hh) * S + qi) * D_;
            wr_split(g_qh, g_ql, dst + d, y1);
            wr_split(g_qh, g_ql, dst + d + 64, y2);
        } else if (hh < H_ + KH_) {
            const int k = hh - H_;
            const float* src = g_qkv + (size_t)t * QKV_N_ + (H_ + k) * D_;
            float x1 = src[d], x2 = src[d + 64];
            float y1 = x1 * c - x2 * s;
            float y2 = x2 * c + x1 * s;
            size_t dst = ((size_t)(b * KH_ + k) * S + qi) * D_;
            wr_split(g_kh, g_kl, dst + d, y1);
            wr_split(g_kh, g_kl, dst + d + 64, y2);
        } else {
            const int v = hh - H_ - KH_;
            const float* src = g_qkv + (size_t)t * QKV_N_ + (H_ + KH_ + v) * D_;
            size_t dst = ((size_t)(b * KH_ + v) * S + qi) * D_;
            wr_split(g_vh, g_vl, dst + d, src[d]);
            wr_split(g_vh, g_vl, dst + d + 64, src[d + 64]);
        }
    }
}

// ------------------------ flash attention (mma.sync) -----------------------
// Unchanged from R15 (best): CTA = 128 queries x 1 head; 8 warps x 16 rows;
// 64-key blocks; 2-stage cp.async; per-warp block skip; exp2 softmax;
// register-resident Q hi/lo fragments.
#define SQH_  0
#define SQL_  32768
#define SSTG_ 65536
#define STGB_ 65536
#define FLASH_SMEM (SSTG_ + 2 * STGB_)   // 196608

__global__ __launch_bounds__(256, 1) void flash_attn(const int* __restrict__ seqp,
                                                     const int* __restrict__ winp)
{
    extern __shared__ __align__(1024) char smf[];
    const uint32_t sb = (uint32_t)__cvta_generic_to_shared(smf);

    const int tid = threadIdx.x, lane = tid & 31, w = tid >> 5;
    const int S = seqp[0], W = winp[0];
    const int tau = blockIdx.x * 128;
    const int h   = blockIdx.y;
    const int b   = tau / S, q0 = tau - b * S;
    const int kvh = h / GROUPS_;

    const __nv_bfloat16* qhg = g_qh + ((size_t)(b * H_ + h) * S + q0) * D_;
    const __nv_bfloat16* qlg = g_ql + ((size_t)(b * H_ + h) * S + q0) * D_;
    const size_t kvb = (size_t)(b * KH_ + kvh) * S * D_;

    // Q (hi+lo) -> smem
#pragma unroll
    for (int i = 0; i < 8; i++) {
        int c = tid + i * 256; int r = c >> 4, sl = c & 15;
        cp16(sb + SQH_ + swz(r, sl), qhg + (size_t)r * D_ + sl * 8);
        cp16(sb + SQL_ + swz(r, sl), qlg + (size_t)r * D_ + sl * 8);
    }
    cp_commit();

    int fk = q0 - W + 1; if (fk < 0) fk = 0;
    const int jb_lo = fk >> 6;
    const int jb_hi = (q0 + 127) >> 6;
    const int nb    = jb_hi - jb_lo + 1;

    // per-warp valid block range (relative indices); barriers stay global
    const int rw0 = q0 + w * 16;
    int wk0 = rw0 - W + 1; if (wk0 < 0) wk0 = 0;
    const int jwlo = (wk0 >> 6) - jb_lo;
    const int jwhi = ((rw0 + 15) >> 6) - jb_lo;

    auto load_stage = [&](int idx) {
        const int jb = jb_lo + idx;
        const uint32_t sg = sb + SSTG_ + (idx & 1) * STGB_;
        const size_t gofs = kvb + (size_t)jb * 64 * D_;
#pragma unroll
        for (int i = 0; i < 4; i++) {
            int c = tid + i * 256; int r = c >> 4, sl = c & 15;
            const uint32_t so = swz(r, sl);
            const size_t go = gofs + (size_t)r * D_ + sl * 8;
            cp16(sg + so,         g_kh + go);
            cp16(sg + 16384 + so, g_kl + go);
            cp16(sg + 32768 + so, g_vh + go);
            cp16(sg + 49152 + so, g_vl + go);
        }
        cp_commit();
    };

    load_stage(0);
    load_stage(1);

    // Q fragments: hi AND lo register-resident (1 CTA/SM -> 256-reg budget)
    cp_wait<2>();
    __syncthreads();
    uint32_t qhf[8][4], qlf[8][4];
    {
        const int r = w * 16 + (lane & 15);
#pragma unroll
        for (int kc = 0; kc < 8; kc++) {
            const uint32_t qso = swz(r, kc * 2 + (lane >> 4));
            ldsm_x4(qhf[kc], sb + SQH_ + qso);
            ldsm_x4(qlf[kc], sb + SQL_ + qso);
        }
    }

    float o[16][4];
#pragma unroll
    for (int i = 0; i < 16; i++)
#pragma unroll
        for (int e = 0; e < 4; e++) o[i][e] = 0.0f;
    float m[2] = {-1e8f, -1e8f}, l[2] = {0.0f, 0.0f};
    const int qrow = q0 + w * 16 + (lane >> 2);

    for (int i = 0; i < nb; i++) {
        if (i + 1 < nb) cp_wait<1>(); else cp_wait<0>();
        __syncthreads();

        if (i >= jwlo && i <= jwhi) {
            const int jb = jb_lo + i;
            const uint32_t stg = sb + SSTG_ + (i & 1) * STGB_;

            // ---- scores ----
            float sc[8][4];
#pragma unroll
            for (int nt = 0; nt < 8; nt++)
#pragma unroll
                for (int e = 0; e < 4; e++) sc[nt][e] = 0.0f;

#pragma unroll
            for (int kc = 0; kc < 8; kc++) {
#pragma unroll
                for (int ntp = 0; ntp < 4; ntp++) {
                    const int r  = ntp * 16 + ((lane >> 4) << 3) + (lane & 7);
                    const int sl = kc * 2 + ((lane >> 3) & 1);
                    uint32_t t4[4];
                    ldsm_x4(t4, stg + swz(r, sl));                     // Khi
                    uint32_t f0[2] = {t4[0], t4[1]}, f1[2] = {t4[2], t4[3]};
                    mma_bf16(sc[2 * ntp],     qhf[kc], f0);
                    mma_bf16(sc[2 * ntp + 1], qhf[kc], f1);
                    mma_bf16(sc[2 * ntp],     qlf[kc], f0);
                    mma_bf16(sc[2 * ntp + 1], qlf[kc], f1);
                    ldsm_x4(t4, stg + 16384 + swz(r, sl));             // Klo
                    uint32_t g0[2] = {t4[0], t4[1]}, g1[2] = {t4[2], t4[3]};
                    mma_bf16(sc[2 * ntp],     qhf[kc], g0);
                    mma_bf16(sc[2 * ntp + 1], qhf[kc], g1);
                }
            }

            // ---- mask (per-warp edge blocks only) ----
            const int j0 = jb * 64;
            if (j0 < rw0 + 16 - W || j0 + 63 > rw0) {
#pragma unroll
                for (int nt = 0; nt < 8; nt++)
#pragma unroll
                    for (int e = 0; e < 4; e++) {
                        const int jg = j0 + nt * 8 + ((lane & 3) << 1) + (e & 1);
                        const int qg = qrow + ((e >> 1) << 3);
                        const int dd = qg - jg;
                        if (dd < 0 || dd >= W) sc[nt][e] = -1e9f;
                    }
            }

            // ---- online softmax (exp2 domain: Q pre-scaled by log2e) ----
            float corr[2];
#pragma unroll
            for (int h2 = 0; h2 < 2; h2++) {
                float bm = -1e30f;
#pragma unroll
                for (int nt = 0; nt < 8; nt++)
                    bm = fmaxf(bm, fmaxf(sc[nt][2 * h2], sc[nt][2 * h2 + 1]));
                bm = fmaxf(bm, __shfl_xor_sync(0xffffffffu, bm, 1));
                bm = fmaxf(bm, __shfl_xor_sync(0xffffffffu, bm, 2));
                const float mn = fmaxf(m[h2], bm);
                corr[h2] = ex2(m[h2] - mn);
                m[h2] = mn;
                l[h2] *= corr[h2];
            }
#pragma unroll
            for (int nt = 0; nt < 8; nt++)
#pragma unroll
                for (int e = 0; e < 4; e++) {
                    const float p = ex2(sc[nt][e] - m[e >> 1]);
                    sc[nt][e] = p;
                    l[e >> 1] += p;
                }
#pragma unroll
            for (int nv = 0; nv < 16; nv++) {
                o[nv][0] *= corr[0]; o[nv][1] *= corr[0];
                o[nv][2] *= corr[1]; o[nv][3] *= corr[1];
            }

            // ---- P fragments (hi/lo) + PV ----
#pragma unroll
            for (int t = 0; t < 4; t++) {
                uint32_t ph[4], pl[4];
                split2(sc[2 * t][0],     sc[2 * t][1],     ph[0], pl[0]);
                split2(sc[2 * t][2],     sc[2 * t][3],     ph[1], pl[1]);
                split2(sc[2 * t + 1][0], sc[2 * t + 1][1], ph[2], pl[2]);
                split2(sc[2 * t + 1][2], sc[2 * t + 1][3], ph[3], pl[3]);
                const int r = t * 16 + (lane & 15);
#pragma unroll
                for (int np = 0; np < 8; np++) {
                    const int sl = np * 2 + (lane >> 4);
                    uint32_t t4[4];
                    ldsm_x4_t(t4, stg + 32768 + swz(r, sl));           // Vhi
                    uint32_t f0[2] = {t4[0], t4[1]}, f1[2] = {t4[2], t4[3]};
                    mma_bf16(o[2 * np],     ph, f0);
                    mma_bf16(o[2 * np + 1], ph, f1);
                    mma_bf16(o[2 * np],     pl, f0);
                    mma_bf16(o[2 * np + 1], pl, f1);
                    ldsm_x4_t(t4, stg + 49152 + swz(r, sl));           // Vlo
                    uint32_t g0[2] = {t4[0], t4[1]}, g1[2] = {t4[2], t4[3]};
                    mma_bf16(o[2 * np],     ph, g0);
                    mma_bf16(o[2 * np + 1], ph, g1);
                }
            }
        }

        __syncthreads();
        if (i + 2 < nb) load_stage(i + 2);
    }

    // quad-reduce row sums (lanes sharing a row own disjoint column partials)
#pragma unroll
    for (int h2 = 0; h2 < 2; h2++) {
        l[h2] += __shfl_xor_sync(0xffffffffu, l[h2], 1);
        l[h2] += __shfl_xor_sync(0xffffffffu, l[h2], 2);
    }

    // ---- epilogue: write hi/lo bf16 directly for the O GEMM ----
    const float inv0 = 1.0f / l[0], inv1 = 1.0f / l[1];
    const size_t t0 = (size_t)b * S + qrow;
    const size_t t1 = t0 + 8;
#pragma unroll
    for (int nv = 0; nv < 16; nv++) {
        const int col = h * D_ + nv * 8 + ((lane & 3) << 1);
        uint32_t hi0, lo0, hi1, lo1;
        split2(o[nv][0] * inv0, o[nv][1] * inv0, hi0, lo0);
        split2(o[nv][2] * inv1, o[nv][3] * inv1, hi1, lo1);
        *(uint32_t*)(g_att_hi + t0 * HIDDEN_ + col) = hi0;
        *(uint32_t*)(g_att_lo + t0 * HIDDEN_ + col) = lo0;
        *(uint32_t*)(g_att_hi + t1 * HIDDEN_ + col) = hi1;
        *(uint32_t*)(g_att_lo + t1 * HIDDEN_ + col) = lo1;
    }
}

// --------------------------------- launch ----------------------------------
extern "C" void kernel_launch(void* const* d_in, const int* in_sizes, int n_in,
                              void* d_out, int out_size)
{
    const float* hs   = (const float*)d_in[0];
    const float* wqkv = (const float*)d_in[1];
    const float* bqkv = (const float*)d_in[2];
    const float* wo   = (const float*)d_in[3];
    const float* bo   = (const float*)d_in[4];
    const float* cosp = (const float*)d_in[5];
    const float* sinp = (const float*)d_in[6];
    const int*   seqp = (const int*)d_in[7];
    const int*   winp = (const int*)d_in[8];
    float*       out  = (float*)d_out;

    const int T = in_sizes[0] / HIDDEN_;

    float* qkvbuf;
    __nv_bfloat16 *hs_hi, *hs_lo, *at_hi, *at_lo, *wq_hi, *wq_lo, *wo_hi, *wo_lo;
    cudaGetSymbolAddress((void**)&qkvbuf, g_qkv);
    cudaGetSymbolAddress((void**)&hs_hi, g_hs_hi);
    cudaGetSymbolAddress((void**)&hs_lo, g_hs_lo);
    cudaGetSymbolAddress((void**)&at_hi, g_att_hi);
    cudaGetSymbolAddress((void**)&at_lo, g_att_lo);
    cudaGetSymbolAddress((void**)&wq_hi, g_wqkv_hi);
    cudaGetSymbolAddress((void**)&wq_lo, g_wqkv_lo);
    cudaGetSymbolAddress((void**)&wo_hi, g_wo_hi);
    cudaGetSymbolAddress((void**)&wo_lo, g_wo_lo);

    cudaFuncSetAttribute(flash_attn, cudaFuncAttributeMaxDynamicSharedMemorySize,
                         FLASH_SMEM);

    // splits
    {
        int n4 = T * HIDDEN_ / 4;
        split_bf16<<<(n4 + 255) / 256, 256>>>(hs, hs_hi, hs_lo, n4);
        n4 = QKV_N_ * HIDDEN_ / 4;
        split_bf16<<<(n4 + 255) / 256, 256>>>(wqkv, wq_hi, wq_lo, n4);
        n4 = HIDDEN_ * HIDDEN_ / 4;
        split_bf16<<<(n4 + 255) / 256, 256>>>(wo, wo_hi, wo_lo, n4);
    }
    // QKV GEMM
    {
        dim3 grid(QKV_N_ / 128, T / 128);
        gemm_mma<<<grid, 256>>>(hs_hi, hs_lo, wq_hi, wq_lo, bqkv,
                                qkvbuf, T, QKV_N_, HIDDEN_);
    }
    // RoPE + scale + split into attention operands
    prep_attn<<<T, 256>>>(cosp, sinp, seqp);
    // flash attention
    {
        dim3 grid(T / 128, H_);
        flash_attn<<<grid, 256, FLASH_SMEM>>>(seqp, winp);
    }
    // O GEMM
    {
        dim3 grid(HIDDEN_ / 128, T / 128);
        gemm_mma<<<grid, 256>>>(at_hi, at_lo, wo_hi, wo_lo, bo,
                                out, T, HIDDEN_, HIDDEN_);
    }
}